// round 1
// baseline (speedup 1.0000x reference)
#include <cuda_runtime.h>
#include <cuda_bf16.h>
#include <math.h>

// ---------------------------------------------------------------------------
// GNNModel: hyperbolic GNN message passing (c = 1e-6)
// Inputs (metadata order):
//  0 hidden     (100000,64) f32
//  1 q_rel      (256,)      i32
//  2 edges      (1000000,6) i32   cols: [r_idx, 0, rel, 0, sub, obj]
//  3 rela_embed (401,64)    f32
//  4 Ws_w (64,64)  5 Wr_w (64,64)  6 Wqr_w (64,64)  7 Wqr_b (64,)
//  8 Wattn_w (1,64)  9 Wh_w (64,64)  10 n_node (scalar)
// Output: (100000,64) f32
// ---------------------------------------------------------------------------

#define MAX_NODE 100000
#define MAX_VOCAB 512
#define MAX_B 256
#define DD 64

__device__ float g_hs_proj[MAX_NODE * DD];   // Ws @ hidden[n]
__device__ float g_hs_h  [MAX_NODE * DD];    // expmap0(hidden[n])
__device__ float g_rel_proj[MAX_VOCAB * DD]; // Wr @ rela_embed[r]
__device__ float g_hr_h   [MAX_VOCAB * DD];  // expmap0(rela_embed[r])
__device__ float g_qr_proj[MAX_B * DD];      // Wqr @ rela_embed[q_rel[b]] + b

__device__ __forceinline__ float warp_sum(float v) {
#pragma unroll
    for (int o = 16; o; o >>= 1) v += __shfl_xor_sync(0xffffffffu, v, o);
    return v;
}

__device__ __forceinline__ float artanh_ref(float x) {
    // clip to [-1+1e-5, 1-1e-5], 0.5*(log1p(x)-log1p(-x))
    x = fminf(fmaxf(x, -1.0f + 1e-5f), 1.0f - 1e-5f);
    return 0.5f * (log1pf(x) - log1pf(-x));
}

// sqrt(c) with c = 1e-6 (f32)
#define SC 1.0e-3f
// maxnorm = (1-0.004)/sqrt(c) — never binding for these magnitudes, kept exact
#define MAXNORM (0.996f / SC)

// ---------------------------------------------------------------------------
// prep: per-row matvec  proj = W @ src[row]  (+bias), optional expmap0 output,
// optional zeroing of out.  32 rows per block of 256 threads (4 rows/iter).
// mode 0: nodes   (proj=g_hs_proj, h=g_hs_h, zero out)
// mode 1: rels    (proj=g_rel_proj, h=g_hr_h)
// mode 2: qr      (proj=g_qr_proj, gather=q_rel, bias=Wqr_b)
// ---------------------------------------------------------------------------
__global__ __launch_bounds__(256) void prep_kernel(
    const float* __restrict__ W, const float* __restrict__ src,
    const int* __restrict__ gidx, const float* __restrict__ bias_p,
    float* __restrict__ outp, int n_rows, int mode)
{
    __shared__ float Wst[DD][DD + 1];  // transposed for conflict-free reads
    __shared__ float hsm[4][DD];

    int t = threadIdx.x;
    for (int i = t; i < DD * DD; i += 256) {
        int r = i >> 6, k = i & 63;
        Wst[k][r] = W[i];
    }

    float* proj; float* hout = nullptr; float* zout = nullptr;
    if (mode == 0)      { proj = g_hs_proj;  hout = g_hs_h; zout = outp; }
    else if (mode == 1) { proj = g_rel_proj; hout = g_hr_h; }
    else                { proj = g_qr_proj; }

    int nl = t >> 6;    // local row slot 0..3
    int j  = t & 63;    // output dim

    for (int it = 0; it < 8; it++) {
        int row = blockIdx.x * 32 + it * 4 + nl;
        bool active = row < n_rows;
        __syncthreads();
        if (active) {
            int srow = (mode == 2) ? gidx[row] : row;
            hsm[nl][j] = src[srow * DD + j];
        }
        __syncthreads();
        if (!active) continue;

        float acc = (mode == 2) ? bias_p[j] : 0.0f;
        float nsq = 0.0f;
#pragma unroll
        for (int k = 0; k < DD; k++) {
            float hk = hsm[nl][k];
            acc = fmaf(Wst[k][j], hk, acc);
            nsq = fmaf(hk, hk, nsq);
        }
        proj[row * DD + j] = acc;

        if (hout) {
            // expmap0(u): tanh(clip(sc*n,±15)) * u / (sc*n), then project
            float n   = fmaxf(sqrtf(nsq), 1e-15f);
            float scn = fminf(SC * n, 15.0f);
            float fac = tanhf(scn) / (SC * n);
            float rn  = fmaxf(fac * n, 1e-15f);   // norm of expmap result
            float ps  = (rn > MAXNORM) ? (MAXNORM / rn) : 1.0f;
            hout[row * DD + j] = fac * ps * hsm[nl][j];
        }
        if (zout) zout[row * DD + j] = 0.0f;
    }
}

// ---------------------------------------------------------------------------
// edge kernel: one warp per edge, lane owns columns (2*lane, 2*lane+1)
// ---------------------------------------------------------------------------
__global__ __launch_bounds__(256) void edge_kernel(
    const int* __restrict__ edges, const float* __restrict__ Wattn,
    float* __restrict__ out, int n_edge)
{
    int warp = (blockIdx.x * blockDim.x + threadIdx.x) >> 5;
    if (warp >= n_edge) return;
    int lane = threadIdx.x & 31;

    const int* e = edges + (long)warp * 6;
    int r_idx = __ldg(e + 0);
    int rel   = __ldg(e + 2);
    int sub   = __ldg(e + 4);
    int obj   = __ldg(e + 5);

    // attention: pre = hs_proj[sub] + rel_proj[rel] + qr_proj[r_idx]
    float2 p  = ((const float2*)g_hs_proj )[sub   * 32 + lane];
    float2 rp = ((const float2*)g_rel_proj)[rel   * 32 + lane];
    float2 qp = ((const float2*)g_qr_proj )[r_idx * 32 + lane];
    float2 wa = __ldg((const float2*)Wattn + lane);

    float t0 = fmaxf(p.x + rp.x + qp.x, 0.0f);
    float t1 = fmaxf(p.y + rp.y + qp.y, 0.0f);
    float s_attn = fmaf(t0, wa.x, t1 * wa.y);

    // mobius_add(hs_h, hr_h)
    float2 x = ((const float2*)g_hs_h)[sub * 32 + lane];
    float2 y = ((const float2*)g_hr_h)[rel * 32 + lane];
    float px2 = fmaf(x.x, x.x, x.y * x.y);
    float py2 = fmaf(y.x, y.x, y.y * y.y);
    float pxy = fmaf(x.x, y.x, x.y * y.y);

    s_attn = warp_sum(s_attn);
    float x2 = warp_sum(px2);
    float y2 = warp_sum(py2);
    float xy = warp_sum(pxy);

    float alpha = 1.0f / (1.0f + expf(-s_attn));

    const float c = 1e-6f;
    float A   = 1.0f + 2.0f * c * xy + c * y2;
    float Bf  = 1.0f - c * x2;
    float den = fmaxf(1.0f + 2.0f * c * xy + c * c * x2 * y2, 1e-15f);
    float m0 = (A * x.x + Bf * y.x) / den;
    float m1 = (A * x.y + Bf * y.y) / den;

    // project + logmap0
    float mm = warp_sum(fmaf(m0, m0, m1 * m1));
    float n  = fmaxf(sqrtf(mm), 1e-15f);
    float ps = (n > MAXNORM) ? (MAXNORM / n) : 1.0f;
    m0 *= ps; m1 *= ps;
    float n2 = fmaxf(fminf(n, MAXNORM), 1e-15f);     // norm after project
    float f  = artanh_ref(SC * n2) / (SC * n2);

    float g0 = m0 * f * alpha;
    float g1 = m1 * f * alpha;

    float* dst = out + (long)obj * DD + lane * 2;
    atomicAdd(dst,     g0);
    atomicAdd(dst + 1, g1);
}

// ---------------------------------------------------------------------------
// final: out[n] = logmap0(relu(expmap0(Wh @ agg[n])))   (in-place on out)
// 32 nodes per block of 256 threads (4 per iter), 64 threads per node.
// ---------------------------------------------------------------------------
__global__ __launch_bounds__(256) void final_kernel(
    const float* __restrict__ Wh, float* __restrict__ out, int n_node)
{
    __shared__ float Wst[DD][DD + 1];
    __shared__ float hsm[4][DD];
    __shared__ float red[8];

    int t = threadIdx.x;
    for (int i = t; i < DD * DD; i += 256) {
        int r = i >> 6, k = i & 63;
        Wst[k][r] = Wh[i];
    }

    int nl = t >> 6;
    int j  = t & 63;
    int w  = t >> 5;        // warp id in block
    int lane = t & 31;

    for (int it = 0; it < 8; it++) {
        int row = blockIdx.x * 32 + it * 4 + nl;
        bool active = row < n_node;
        __syncthreads();
        if (active) hsm[nl][j] = out[row * DD + j];
        __syncthreads();

        float acc = 0.0f;
        if (active) {
#pragma unroll
            for (int k = 0; k < DD; k++)
                acc = fmaf(Wst[k][j], hsm[nl][k], acc);
        }

        // ||v||^2 over the 64-thread group (2 warps)
        float pv = warp_sum(acc * acc);
        if (lane == 0) red[w] = pv;
        __syncthreads();
        float nv2 = red[nl * 2] + red[nl * 2 + 1];
        __syncthreads();

        float nv  = fmaxf(sqrtf(nv2), 1e-15f);
        float fac = tanhf(fminf(SC * nv, 15.0f)) / (SC * nv);
        float rn  = fmaxf(fac * nv, 1e-15f);
        float ps  = (rn > MAXNORM) ? (MAXNORM / rn) : 1.0f;
        float a   = fmaxf(acc * fac * ps, 0.0f);   // relu(expmap0(v))

        float pa = warp_sum(a * a);
        if (lane == 0) red[w] = pa;
        __syncthreads();
        float na2 = red[nl * 2] + red[nl * 2 + 1];

        float na = fmaxf(sqrtf(na2), 1e-15f);
        float g  = artanh_ref(SC * na) / (SC * na);
        if (active) out[row * DD + j] = a * g;
    }
}

// ---------------------------------------------------------------------------
extern "C" void kernel_launch(void* const* d_in, const int* in_sizes, int n_in,
                              void* d_out, int out_size)
{
    const float* hidden = (const float*)d_in[0];
    const int*   q_rel  = (const int*)  d_in[1];
    const int*   edges  = (const int*)  d_in[2];
    const float* rela   = (const float*)d_in[3];
    const float* Ws     = (const float*)d_in[4];
    const float* Wr     = (const float*)d_in[5];
    const float* Wqr    = (const float*)d_in[6];
    const float* Wqr_b  = (const float*)d_in[7];
    const float* Wattn  = (const float*)d_in[8];
    const float* Wh     = (const float*)d_in[9];
    float* out = (float*)d_out;

    int n_node  = in_sizes[0] / DD;
    int Bn      = in_sizes[1];
    int n_edge  = in_sizes[2] / 6;
    int n_vocab = in_sizes[3] / DD;

    // precompute tables (also zeros d_out in mode 0)
    prep_kernel<<<(n_node  + 31) / 32, 256>>>(Ws,  hidden, nullptr, nullptr, out, n_node,  0);
    prep_kernel<<<(n_vocab + 31) / 32, 256>>>(Wr,  rela,   nullptr, nullptr, out, n_vocab, 1);
    prep_kernel<<<(Bn      + 31) / 32, 256>>>(Wqr, rela,   q_rel,   Wqr_b,   out, Bn,      2);

    // 1 warp per edge, 8 edges per block
    edge_kernel<<<(n_edge + 7) / 8, 256>>>(edges, Wattn, out, n_edge);

    // per-node epilogue (in-place on out)
    final_kernel<<<(n_node + 31) / 32, 256>>>(Wh, out, n_node);
}

// round 2
// speedup vs baseline: 1.4831x; 1.4831x over previous
#include <cuda_runtime.h>
#include <cuda_bf16.h>
#include <math.h>

// ---------------------------------------------------------------------------
// GNNModel: hyperbolic GNN message passing (c = 1e-6)
// ---------------------------------------------------------------------------

#define MAX_NODE 100000
#define MAX_VOCAB 512
#define MAX_B 256
#define DD 64
#define TILES 4

__device__ float g_hs_proj[MAX_NODE * DD];   // Ws @ hidden[n]
__device__ float g_hs_h  [MAX_NODE * DD];    // expmap0(hidden[n])
__device__ float g_hs_x2 [MAX_NODE];         // ||expmap0(hidden[n])||^2
__device__ float g_rel_proj[MAX_VOCAB * DD]; // Wr @ rela_embed[r]
__device__ float g_hr_h   [MAX_VOCAB * DD];  // expmap0(rela_embed[r])
__device__ float g_hr_y2  [MAX_VOCAB];       // ||expmap0(rela_embed[r])||^2
__device__ float g_qr_proj[MAX_B * DD];      // Wqr @ rela_embed[q_rel[b]] + b

#define SC 1.0e-3f                 // sqrt(c), c = 1e-6
#define MAXNORM (0.996f / SC)      // (1 - 0.004)/sqrt(c)

__device__ __forceinline__ float artanh_ref(float x) {
    x = fminf(fmaxf(x, -1.0f + 1e-5f), 1.0f - 1e-5f);
    return 0.5f * (log1pf(x) - log1pf(-x));
}

// ---------------------------------------------------------------------------
// prep: proj[row] = W @ src[row] (+bias); optional expmap0 + norm^2 tables.
// Register-tiled: 256 threads, 16 rows per tile, thread (g = t>>6, j = t&63)
// computes column j for 4 rows; h staged transposed so one broadcast
// ld.shared.v4 feeds 4 FMAs; W read once per (k, j) for 4 rows.
// mode 0: nodes (also zeroes zout)   mode 1: rels   mode 2: qr (gather+bias)
// ---------------------------------------------------------------------------
__global__ __launch_bounds__(256) void prep_kernel(
    const float* __restrict__ W, const float* __restrict__ src,
    const int* __restrict__ gidx, const float* __restrict__ bias_p,
    float* __restrict__ zout, int n_rows, int mode)
{
    __shared__ float Wst[DD][DD + 1];              // Wst[k][j] = W[j*64+k]
    __shared__ __align__(16) float hT[4][DD * 4];  // hT[g][k*4 + r]
    __shared__ float red2[4][2][4];

    int t = threadIdx.x;
    for (int i = t; i < DD * DD; i += 256) Wst[i & 63][i >> 6] = W[i];

    float* proj; float* hout = nullptr; float* x2out = nullptr;
    if (mode == 0)      { proj = g_hs_proj;  hout = g_hs_h; x2out = g_hs_x2; }
    else if (mode == 1) { proj = g_rel_proj; hout = g_hr_h; x2out = g_hr_y2; }
    else                { proj = g_qr_proj; }

    int g = t >> 6, j = t & 63, half = (t >> 5) & 1;
    float bias = (mode == 2) ? bias_p[j] : 0.0f;

    for (int tile = 0; tile < TILES; tile++) {
        int base = (blockIdx.x * TILES + tile) * 16;
        if (base >= n_rows) break;
        __syncthreads();
        // stage 16 rows, transposed per 4-row group
        for (int i = t; i < 1024; i += 256) {
            int r16 = i >> 6, k = i & 63;
            int row = base + r16;
            float v = 0.0f;
            if (row < n_rows) {
                int sr = (mode == 2) ? gidx[row] : row;
                v = src[sr * DD + k];
            }
            hT[r16 >> 2][k * 4 + (r16 & 3)] = v;
        }
        __syncthreads();

        // per-row ||u||^2 via reduction over j
        float4 hj = *(const float4*)&hT[g][j * 4];
        float s0 = hj.x * hj.x, s1 = hj.y * hj.y, s2 = hj.z * hj.z, s3 = hj.w * hj.w;
#pragma unroll
        for (int o = 16; o; o >>= 1) {
            s0 += __shfl_xor_sync(0xffffffffu, s0, o);
            s1 += __shfl_xor_sync(0xffffffffu, s1, o);
            s2 += __shfl_xor_sync(0xffffffffu, s2, o);
            s3 += __shfl_xor_sync(0xffffffffu, s3, o);
        }
        if ((t & 31) == 0) {
            red2[g][half][0] = s0; red2[g][half][1] = s1;
            red2[g][half][2] = s2; red2[g][half][3] = s3;
        }
        __syncthreads();
        float nsq[4];
#pragma unroll
        for (int r = 0; r < 4; r++) nsq[r] = red2[g][0][r] + red2[g][1][r];

        // matvec: 4 rows per thread
        float a0 = bias, a1 = bias, a2 = bias, a3 = bias;
#pragma unroll
        for (int k = 0; k < DD; k++) {
            float w = Wst[k][j];
            float4 h4 = *(const float4*)&hT[g][k * 4];
            a0 = fmaf(w, h4.x, a0); a1 = fmaf(w, h4.y, a1);
            a2 = fmaf(w, h4.z, a2); a3 = fmaf(w, h4.w, a3);
        }
        float acc[4] = {a0, a1, a2, a3};
        float hv[4]  = {hj.x, hj.y, hj.z, hj.w};

#pragma unroll
        for (int r = 0; r < 4; r++) {
            int row = base + g * 4 + r;
            if (row >= n_rows) continue;
            proj[row * DD + j] = acc[r];
            if (hout) {
                float n   = fmaxf(sqrtf(nsq[r]), 1e-15f);
                float fac = tanhf(fminf(SC * n, 15.0f)) / (SC * n);
                float rn  = fmaxf(fac * n, 1e-15f);
                float ps  = (rn > MAXNORM) ? (MAXNORM / rn) : 1.0f;
                hout[row * DD + j] = fac * ps * hv[r];
                if (j == 0) {
                    float nh = fminf(rn, MAXNORM);
                    x2out[row] = nh * nh;
                }
            }
            if (mode == 0) zout[row * DD + j] = 0.0f;
        }
    }
}

// ---------------------------------------------------------------------------
// edge kernel: 16 lanes per edge (2 edges/warp), lane owns 4 columns (float4).
// x2/y2 precomputed; ||m||^2 computed algebraically -> only 2 reductions.
// Scatter via red.global.add.v4.f32.
// ---------------------------------------------------------------------------
__global__ __launch_bounds__(256) void edge_kernel(
    const int* __restrict__ edges, const float* __restrict__ Wattn,
    float* __restrict__ out, int n_edge)
{
    int l = threadIdx.x & 15;
    float4 wa = __ldg((const float4*)Wattn + l);
    int group  = (blockIdx.x * blockDim.x + threadIdx.x) >> 4;
    int stride = (gridDim.x * blockDim.x) >> 4;
    const float c = 1e-6f;

    for (int e = group; e < n_edge; e += stride) {
        const int2* ep = (const int2*)edges + (long)e * 3;
        int2 w0 = __ldg(ep), w1 = __ldg(ep + 1), w2 = __ldg(ep + 2);
        int r_idx = w0.x, rel = w1.x, sub = w2.x, obj = w2.y;

        float4 p  = __ldg((const float4*)g_hs_proj  + sub   * 16 + l);
        float4 rp = __ldg((const float4*)g_rel_proj + rel   * 16 + l);
        float4 qp = __ldg((const float4*)g_qr_proj  + r_idx * 16 + l);

        float s =      fmaxf(p.x + rp.x + qp.x, 0.0f) * wa.x;
        s = fmaf(fmaxf(p.y + rp.y + qp.y, 0.0f), wa.y, s);
        s = fmaf(fmaxf(p.z + rp.z + qp.z, 0.0f), wa.z, s);
        s = fmaf(fmaxf(p.w + rp.w + qp.w, 0.0f), wa.w, s);

        float4 x = __ldg((const float4*)g_hs_h + sub * 16 + l);
        float4 y = __ldg((const float4*)g_hr_h + rel * 16 + l);
        float pxy = x.x * y.x;
        pxy = fmaf(x.y, y.y, pxy);
        pxy = fmaf(x.z, y.z, pxy);
        pxy = fmaf(x.w, y.w, pxy);

#pragma unroll
        for (int o = 8; o; o >>= 1) {
            s   += __shfl_xor_sync(0xffffffffu, s,   o);
            pxy += __shfl_xor_sync(0xffffffffu, pxy, o);
        }

        float x2 = __ldg(&g_hs_x2[sub]);
        float y2 = __ldg(&g_hr_y2[rel]);

        float alpha = 1.0f / (1.0f + expf(-s));
        float A   = 1.0f + 2.0f * c * pxy + c * y2;
        float B   = 1.0f - c * x2;
        float den = fmaxf(1.0f + 2.0f * c * pxy + c * c * x2 * y2, 1e-15f);
        float inv = 1.0f / den;
        // ||m||^2 = (A^2 x2 + 2AB xy + B^2 y2) / den^2
        float mm = (A * A * x2 + 2.0f * A * B * pxy + B * B * y2) * inv * inv;
        float n  = fmaxf(sqrtf(fmaxf(mm, 0.0f)), 1e-15f);
        float ps = (n > MAXNORM) ? (MAXNORM / n) : 1.0f;
        float n2 = fminf(n, MAXNORM);
        float f  = artanh_ref(SC * n2) / (SC * n2);
        float sc = alpha * f * ps * inv;
        float sA = A * sc, sB = B * sc;

        float g0 = fmaf(sA, x.x, sB * y.x);
        float g1 = fmaf(sA, x.y, sB * y.y);
        float g2 = fmaf(sA, x.z, sB * y.z);
        float g3 = fmaf(sA, x.w, sB * y.w);

        float* dst = out + (long)obj * DD + l * 4;
        asm volatile("red.global.add.v4.f32 [%0], {%1,%2,%3,%4};"
                     :: "l"(dst), "f"(g0), "f"(g1), "f"(g2), "f"(g3) : "memory");
    }
}

// ---------------------------------------------------------------------------
// final: out[n] = logmap0(relu(expmap0(Wh @ agg[n])))  — same tiling as prep
// ---------------------------------------------------------------------------
__global__ __launch_bounds__(256) void final_kernel(
    const float* __restrict__ Wh, float* __restrict__ out, int n_node)
{
    __shared__ float Wst[DD][DD + 1];
    __shared__ __align__(16) float hT[4][DD * 4];
    __shared__ float red2[4][2][4];

    int t = threadIdx.x;
    for (int i = t; i < DD * DD; i += 256) Wst[i & 63][i >> 6] = Wh[i];

    int g = t >> 6, j = t & 63, half = (t >> 5) & 1;

    for (int tile = 0; tile < TILES; tile++) {
        int base = (blockIdx.x * TILES + tile) * 16;
        if (base >= n_node) break;
        __syncthreads();
        for (int i = t; i < 1024; i += 256) {
            int r16 = i >> 6, k = i & 63;
            int row = base + r16;
            hT[r16 >> 2][k * 4 + (r16 & 3)] = (row < n_node) ? out[row * DD + k] : 0.0f;
        }
        __syncthreads();

        float a0 = 0, a1 = 0, a2 = 0, a3 = 0;
#pragma unroll
        for (int k = 0; k < DD; k++) {
            float w = Wst[k][j];
            float4 h4 = *(const float4*)&hT[g][k * 4];
            a0 = fmaf(w, h4.x, a0); a1 = fmaf(w, h4.y, a1);
            a2 = fmaf(w, h4.z, a2); a3 = fmaf(w, h4.w, a3);
        }
        float acc[4] = {a0, a1, a2, a3};

        // reduction 1: ||v||^2 per row
        float s0 = a0 * a0, s1 = a1 * a1, s2 = a2 * a2, s3 = a3 * a3;
#pragma unroll
        for (int o = 16; o; o >>= 1) {
            s0 += __shfl_xor_sync(0xffffffffu, s0, o);
            s1 += __shfl_xor_sync(0xffffffffu, s1, o);
            s2 += __shfl_xor_sync(0xffffffffu, s2, o);
            s3 += __shfl_xor_sync(0xffffffffu, s3, o);
        }
        if ((t & 31) == 0) {
            red2[g][half][0] = s0; red2[g][half][1] = s1;
            red2[g][half][2] = s2; red2[g][half][3] = s3;
        }
        __syncthreads();
        float av[4];
#pragma unroll
        for (int r = 0; r < 4; r++) {
            float nv2 = red2[g][0][r] + red2[g][1][r];
            float nv  = fmaxf(sqrtf(nv2), 1e-15f);
            float fac = tanhf(fminf(SC * nv, 15.0f)) / (SC * nv);
            float rn  = fmaxf(fac * nv, 1e-15f);
            float ps  = (rn > MAXNORM) ? (MAXNORM / rn) : 1.0f;
            av[r] = fmaxf(acc[r] * fac * ps, 0.0f);   // relu(expmap0(v))_j
        }
        __syncthreads();  // red2 reuse

        // reduction 2: ||a||^2 per row
        s0 = av[0] * av[0]; s1 = av[1] * av[1]; s2 = av[2] * av[2]; s3 = av[3] * av[3];
#pragma unroll
        for (int o = 16; o; o >>= 1) {
            s0 += __shfl_xor_sync(0xffffffffu, s0, o);
            s1 += __shfl_xor_sync(0xffffffffu, s1, o);
            s2 += __shfl_xor_sync(0xffffffffu, s2, o);
            s3 += __shfl_xor_sync(0xffffffffu, s3, o);
        }
        if ((t & 31) == 0) {
            red2[g][half][0] = s0; red2[g][half][1] = s1;
            red2[g][half][2] = s2; red2[g][half][3] = s3;
        }
        __syncthreads();
#pragma unroll
        for (int r = 0; r < 4; r++) {
            int row = base + g * 4 + r;
            if (row >= n_node) continue;
            float na2 = red2[g][0][r] + red2[g][1][r];
            float na  = fmaxf(sqrtf(na2), 1e-15f);
            float gg  = artanh_ref(SC * na) / (SC * na);
            out[row * DD + j] = av[r] * gg;
        }
    }
}

// ---------------------------------------------------------------------------
extern "C" void kernel_launch(void* const* d_in, const int* in_sizes, int n_in,
                              void* d_out, int out_size)
{
    const float* hidden = (const float*)d_in[0];
    const int*   q_rel  = (const int*)  d_in[1];
    const int*   edges  = (const int*)  d_in[2];
    const float* rela   = (const float*)d_in[3];
    const float* Ws     = (const float*)d_in[4];
    const float* Wr     = (const float*)d_in[5];
    const float* Wqr    = (const float*)d_in[6];
    const float* Wqr_b  = (const float*)d_in[7];
    const float* Wattn  = (const float*)d_in[8];
    const float* Wh     = (const float*)d_in[9];
    float* out = (float*)d_out;

    int n_node  = in_sizes[0] / DD;
    int Bn      = in_sizes[1];
    int n_edge  = in_sizes[2] / 6;
    int n_vocab = in_sizes[3] / DD;

    prep_kernel<<<(n_node  + 63) / 64, 256>>>(Ws,  hidden, nullptr, nullptr, out,     n_node,  0);
    prep_kernel<<<(n_vocab + 63) / 64, 256>>>(Wr,  rela,   nullptr, nullptr, nullptr, n_vocab, 1);
    prep_kernel<<<(Bn      + 63) / 64, 256>>>(Wqr, rela,   q_rel,   Wqr_b,   nullptr, Bn,      2);

    edge_kernel<<<2368, 256>>>(edges, Wattn, out, n_edge);

    final_kernel<<<(n_node + 63) / 64, 256>>>(Wh, out, n_node);
}

// round 3
// speedup vs baseline: 1.7563x; 1.1842x over previous
#include <cuda_runtime.h>
#include <cuda_bf16.h>
#include <math.h>

// ---------------------------------------------------------------------------
// GNNModel: hyperbolic GNN message passing (c = 1e-6)
// ---------------------------------------------------------------------------

#define MAX_NODE 100000
#define MAX_VOCAB 512
#define MAX_B 256
#define DD 64
#define TILES 4

__device__ float  g_hs_proj[MAX_NODE * DD];   // Ws @ hidden[n]
__device__ float2 g_hs_sc  [MAX_NODE];        // (fac*ps, ||expmap0||^2 clamped)
__device__ float  g_rel_proj[MAX_VOCAB * DD]; // Wr @ rela_embed[r]
__device__ float  g_hr_h   [MAX_VOCAB * DD];  // expmap0(rela_embed[r]) projected
__device__ float  g_hr_y2  [MAX_VOCAB];       // ||hr_h||^2
__device__ float  g_qr_proj[MAX_B * DD];      // Wqr @ rela_embed[q_rel[b]] + b

#define SC 1.0e-3f                    // sqrt(c), c = 1e-6
#define CC 1.0e-6f
#define MAXNORM (0.996f / SC)
#define MN2 (MAXNORM * MAXNORM)

// ---- packed f32x2 helpers ----
__device__ __forceinline__ unsigned long long pack2(float a, float b) {
    unsigned long long r;
    asm("mov.b64 %0, {%1, %2};" : "=l"(r)
        : "r"(__float_as_uint(a)), "r"(__float_as_uint(b)));
    return r;
}
__device__ __forceinline__ void unpack2(unsigned long long v, float& a, float& b) {
    unsigned lo, hi;
    asm("mov.b64 {%0, %1}, %2;" : "=r"(lo), "=r"(hi) : "l"(v));
    a = __uint_as_float(lo); b = __uint_as_float(hi);
}
__device__ __forceinline__ unsigned long long fma2(
    unsigned long long a, unsigned long long b, unsigned long long c) {
    unsigned long long d;
    asm("fma.rn.f32x2 %0, %1, %2, %3;" : "=l"(d) : "l"(a), "l"(b), "l"(c));
    return d;
}

// artanh(z)/z as poly in z^2 (valid z^2 < 0.09, guarded fallback above)
__device__ __forceinline__ float artanh_ratio(float z2) {
    float f = fmaf(z2, fmaf(z2, fmaf(z2, fmaf(z2, 1.0f/9.0f, 1.0f/7.0f),
                                     0.2f), 1.0f/3.0f), 1.0f);
    if (z2 > 0.09f) {                 // z > 0.3 : exact reference path (rare)
        float z = sqrtf(z2);
        float zc = fminf(z, 1.0f - 1e-5f);
        f = 0.5f * (log1pf(zc) - log1pf(-zc)) / z;
    }
    return f;
}
// tanh(z)/z as poly in z^2 (valid z^2 < 0.09, guarded)
__device__ __forceinline__ float tanh_ratio(float z2) {
    float f = fmaf(z2, fmaf(z2, fmaf(z2, -17.0f/315.0f, 2.0f/15.0f),
                            -1.0f/3.0f), 1.0f);
    if (z2 > 0.09f) {
        float z = sqrtf(z2);
        f = tanhf(fminf(z, 15.0f)) / z;
    }
    return f;
}

// ---------------------------------------------------------------------------
// prep: proj[row] = W @ src[row] (+bias); norm tables.
// mode 0: nodes -> g_hs_proj, g_hs_sc, zero zout
// mode 1: rels  -> g_rel_proj, g_hr_h, g_hr_y2
// mode 2: qr    -> g_qr_proj (gather + bias)
// ---------------------------------------------------------------------------
__global__ __launch_bounds__(256) void prep_kernel(
    const float* __restrict__ W, const float* __restrict__ src,
    const int* __restrict__ gidx, const float* __restrict__ bias_p,
    float* __restrict__ zout, int n_rows, int mode)
{
    __shared__ float Wst[DD][DD + 1];              // Wst[k][j] = W[j*64+k]
    __shared__ __align__(16) float hT[4][DD * 4];  // hT[g][k*4 + r]
    __shared__ float red2[4][2][4];

    int t = threadIdx.x;
    for (int i = t; i < DD * DD; i += 256) Wst[i & 63][i >> 6] = W[i];

    float* proj;
    if (mode == 0)      proj = g_hs_proj;
    else if (mode == 1) proj = g_rel_proj;
    else                proj = g_qr_proj;

    int g = t >> 6, j = t & 63, half = (t >> 5) & 1;
    float bias = (mode == 2) ? bias_p[j] : 0.0f;

    for (int tile = 0; tile < TILES; tile++) {
        int base = (blockIdx.x * TILES + tile) * 16;
        if (base >= n_rows) break;
        __syncthreads();
        for (int i = t; i < 1024; i += 256) {
            int r16 = i >> 6, k = i & 63;
            int row = base + r16;
            float v = 0.0f;
            if (row < n_rows) {
                int sr = (mode == 2) ? gidx[row] : row;
                v = src[sr * DD + k];
            }
            hT[r16 >> 2][k * 4 + (r16 & 3)] = v;
        }
        __syncthreads();

        // per-row ||u||^2
        float4 hj = *(const float4*)&hT[g][j * 4];
        float s0 = hj.x * hj.x, s1 = hj.y * hj.y, s2 = hj.z * hj.z, s3 = hj.w * hj.w;
#pragma unroll
        for (int o = 16; o; o >>= 1) {
            s0 += __shfl_xor_sync(0xffffffffu, s0, o);
            s1 += __shfl_xor_sync(0xffffffffu, s1, o);
            s2 += __shfl_xor_sync(0xffffffffu, s2, o);
            s3 += __shfl_xor_sync(0xffffffffu, s3, o);
        }
        if ((t & 31) == 0) {
            red2[g][half][0] = s0; red2[g][half][1] = s1;
            red2[g][half][2] = s2; red2[g][half][3] = s3;
        }
        __syncthreads();
        float nsq[4];
#pragma unroll
        for (int r = 0; r < 4; r++) nsq[r] = red2[g][0][r] + red2[g][1][r];

        // matvec via packed f32x2: rows (0,1) and (2,3)
        unsigned long long acc01 = pack2(bias, bias), acc23 = pack2(bias, bias);
#pragma unroll
        for (int k = 0; k < DD; k++) {
            float w = Wst[k][j];
            unsigned long long ww = pack2(w, w);
            ulonglong2 hh = *(const ulonglong2*)&hT[g][k * 4];
            acc01 = fma2(ww, hh.x, acc01);
            acc23 = fma2(ww, hh.y, acc23);
        }
        float acc[4];
        unpack2(acc01, acc[0], acc[1]);
        unpack2(acc23, acc[2], acc[3]);
        float hv[4] = {hj.x, hj.y, hj.z, hj.w};

#pragma unroll
        for (int r = 0; r < 4; r++) {
            int row = base + g * 4 + r;
            if (row >= n_rows) continue;
            proj[row * DD + j] = acc[r];
            if (mode != 2) {
                float z2  = CC * nsq[r];
                float fac = tanh_ratio(z2);
                float rn2 = fac * fac * nsq[r];          // ||expmap0||^2
                float ps  = 1.0f;
                if (rn2 > MN2) ps = MAXNORM * rsqrtf(rn2);
                float fp  = fac * ps;
                float x2c = fminf(rn2, MN2);
                if (mode == 1) {
                    g_hr_h[row * DD + j] = fp * hv[r];
                    if (j == 0) g_hr_y2[row] = x2c;
                } else {
                    if (j == 0) g_hs_sc[row] = make_float2(fp, x2c);
                }
            }
            if (mode == 0) zout[row * DD + j] = 0.0f;
        }
    }
}

// ---------------------------------------------------------------------------
// edge kernel: 16 lanes per edge (2 edges/warp), lane owns 4 columns.
// x reconstructed as fac_s * hidden[sub]; all transcendentals poly'd.
// ---------------------------------------------------------------------------
__global__ __launch_bounds__(256) void edge_kernel(
    const int* __restrict__ edges, const float* __restrict__ Wattn,
    const float* __restrict__ hidden, float* __restrict__ out, int n_edge)
{
    int l = threadIdx.x & 15;
    float4 wa = __ldg((const float4*)Wattn + l);
    int group  = (blockIdx.x * blockDim.x + threadIdx.x) >> 4;
    int stride = (gridDim.x * blockDim.x) >> 4;

    for (int e = group; e < n_edge; e += stride) {
        const int2* ep = (const int2*)edges + (long)e * 3;
        int2 w0 = __ldg(ep), w1 = __ldg(ep + 1), w2 = __ldg(ep + 2);
        int r_idx = w0.x, rel = w1.x, sub = w2.x, obj = w2.y;

        float4 p  = __ldg((const float4*)g_hs_proj  + sub   * 16 + l);
        float4 rp = __ldg((const float4*)g_rel_proj + rel   * 16 + l);
        float4 qp = __ldg((const float4*)g_qr_proj  + r_idx * 16 + l);

        float s =      fmaxf(p.x + rp.x + qp.x, 0.0f) * wa.x;
        s = fmaf(fmaxf(p.y + rp.y + qp.y, 0.0f), wa.y, s);
        s = fmaf(fmaxf(p.z + rp.z + qp.z, 0.0f), wa.z, s);
        s = fmaf(fmaxf(p.w + rp.w + qp.w, 0.0f), wa.w, s);

        float4 hx = __ldg((const float4*)hidden + sub * 16 + l);
        float4 y  = __ldg((const float4*)g_hr_h + rel * 16 + l);
        float pd = hx.x * y.x;
        pd = fmaf(hx.y, y.y, pd);
        pd = fmaf(hx.z, y.z, pd);
        pd = fmaf(hx.w, y.w, pd);

#pragma unroll
        for (int o = 8; o; o >>= 1) {
            s  += __shfl_xor_sync(0xffffffffu, s,  o);
            pd += __shfl_xor_sync(0xffffffffu, pd, o);
        }

        float2 scs = __ldg(&g_hs_sc[sub]);      // (fac_s, x2)
        float y2 = __ldg(&g_hr_y2[rel]);
        float x2 = scs.y;
        float xy = scs.x * pd;

        float alpha = __fdividef(1.0f, 1.0f + __expf(-s));

        float A   = 1.0f + 2.0f * CC * xy + CC * y2;
        float B   = 1.0f - CC * x2;
        float den = fmaxf(1.0f + 2.0f * CC * xy + CC * CC * x2 * y2, 1e-15f);
        float inv = __fdividef(1.0f, den);
        // ||m||^2 = (A^2 x2 + 2AB xy + B^2 y2) / den^2
        float mm = fmaf(A * A, x2, fmaf(2.0f * A * B, xy, B * B * y2)) * inv * inv;
        mm = fmaxf(mm, 0.0f);
        float ps = 1.0f;
        if (mm > MN2) ps = MAXNORM * rsqrtf(mm);
        float z2 = CC * fminf(mm, MN2);
        float f  = artanh_ratio(z2);

        float sc = alpha * f * ps * inv;
        float sA = A * sc * scs.x;               // fold fac_s into x term
        float sB = B * sc;

        float g0 = fmaf(sA, hx.x, sB * y.x);
        float g1 = fmaf(sA, hx.y, sB * y.y);
        float g2 = fmaf(sA, hx.z, sB * y.z);
        float g3 = fmaf(sA, hx.w, sB * y.w);

        float* dst = out + (long)obj * DD + l * 4;
        asm volatile("red.global.add.v4.f32 [%0], {%1,%2,%3,%4};"
                     :: "l"(dst), "f"(g0), "f"(g1), "f"(g2), "f"(g3) : "memory");
    }
}

// ---------------------------------------------------------------------------
// final: out[n] = logmap0(relu(expmap0(Wh @ agg[n])))  (in-place)
// ---------------------------------------------------------------------------
__global__ __launch_bounds__(256) void final_kernel(
    const float* __restrict__ Wh, float* __restrict__ out, int n_node)
{
    __shared__ float Wst[DD][DD + 1];
    __shared__ __align__(16) float hT[4][DD * 4];
    __shared__ float red2[4][2][4];

    int t = threadIdx.x;
    for (int i = t; i < DD * DD; i += 256) Wst[i & 63][i >> 6] = Wh[i];

    int g = t >> 6, j = t & 63, half = (t >> 5) & 1;

    for (int tile = 0; tile < TILES; tile++) {
        int base = (blockIdx.x * TILES + tile) * 16;
        if (base >= n_node) break;
        __syncthreads();
        for (int i = t; i < 1024; i += 256) {
            int r16 = i >> 6, k = i & 63;
            int row = base + r16;
            hT[r16 >> 2][k * 4 + (r16 & 3)] = (row < n_node) ? out[row * DD + k] : 0.0f;
        }
        __syncthreads();

        unsigned long long acc01 = 0ull, acc23 = 0ull;  // (0.0f,0.0f) packed
#pragma unroll
        for (int k = 0; k < DD; k++) {
            float w = Wst[k][j];
            unsigned long long ww = pack2(w, w);
            ulonglong2 hh = *(const ulonglong2*)&hT[g][k * 4];
            acc01 = fma2(ww, hh.x, acc01);
            acc23 = fma2(ww, hh.y, acc23);
        }
        float acc[4];
        unpack2(acc01, acc[0], acc[1]);
        unpack2(acc23, acc[2], acc[3]);

        // reduction 1: ||v||^2 per row
        float s0 = acc[0]*acc[0], s1 = acc[1]*acc[1], s2 = acc[2]*acc[2], s3 = acc[3]*acc[3];
#pragma unroll
        for (int o = 16; o; o >>= 1) {
            s0 += __shfl_xor_sync(0xffffffffu, s0, o);
            s1 += __shfl_xor_sync(0xffffffffu, s1, o);
            s2 += __shfl_xor_sync(0xffffffffu, s2, o);
            s3 += __shfl_xor_sync(0xffffffffu, s3, o);
        }
        if ((t & 31) == 0) {
            red2[g][half][0] = s0; red2[g][half][1] = s1;
            red2[g][half][2] = s2; red2[g][half][3] = s3;
        }
        __syncthreads();
        float av[4];
#pragma unroll
        for (int r = 0; r < 4; r++) {
            float nv2 = red2[g][0][r] + red2[g][1][r];
            float z2  = CC * nv2;
            float fac = tanh_ratio(z2);
            float rn2 = fac * fac * nv2;
            float ps  = 1.0f;
            if (rn2 > MN2) ps = MAXNORM * rsqrtf(rn2);
            av[r] = fmaxf(acc[r] * fac * ps, 0.0f);      // relu(expmap0(v))_j
        }
        __syncthreads();  // red2 reuse

        // reduction 2: ||a||^2 per row
        s0 = av[0]*av[0]; s1 = av[1]*av[1]; s2 = av[2]*av[2]; s3 = av[3]*av[3];
#pragma unroll
        for (int o = 16; o; o >>= 1) {
            s0 += __shfl_xor_sync(0xffffffffu, s0, o);
            s1 += __shfl_xor_sync(0xffffffffu, s1, o);
            s2 += __shfl_xor_sync(0xffffffffu, s2, o);
            s3 += __shfl_xor_sync(0xffffffffu, s3, o);
        }
        if ((t & 31) == 0) {
            red2[g][half][0] = s0; red2[g][half][1] = s1;
            red2[g][half][2] = s2; red2[g][half][3] = s3;
        }
        __syncthreads();
#pragma unroll
        for (int r = 0; r < 4; r++) {
            int row = base + g * 4 + r;
            if (row >= n_node) continue;
            float na2 = red2[g][0][r] + red2[g][1][r];
            float z2  = CC * na2;
            float gg  = artanh_ratio(z2);
            out[row * DD + j] = av[r] * gg;
        }
    }
}

// ---------------------------------------------------------------------------
extern "C" void kernel_launch(void* const* d_in, const int* in_sizes, int n_in,
                              void* d_out, int out_size)
{
    const float* hidden = (const float*)d_in[0];
    const int*   q_rel  = (const int*)  d_in[1];
    const int*   edges  = (const int*)  d_in[2];
    const float* rela   = (const float*)d_in[3];
    const float* Ws     = (const float*)d_in[4];
    const float* Wr     = (const float*)d_in[5];
    const float* Wqr    = (const float*)d_in[6];
    const float* Wqr_b  = (const float*)d_in[7];
    const float* Wattn  = (const float*)d_in[8];
    const float* Wh     = (const float*)d_in[9];
    float* out = (float*)d_out;

    int n_node  = in_sizes[0] / DD;
    int Bn      = in_sizes[1];
    int n_edge  = in_sizes[2] / 6;
    int n_vocab = in_sizes[3] / DD;

    prep_kernel<<<(n_node  + 63) / 64, 256>>>(Ws,  hidden, nullptr, nullptr, out,     n_node,  0);
    prep_kernel<<<(n_vocab + 63) / 64, 256>>>(Wr,  rela,   nullptr, nullptr, nullptr, n_vocab, 1);
    prep_kernel<<<(Bn      + 63) / 64, 256>>>(Wqr, rela,   q_rel,   Wqr_b,   nullptr, Bn,      2);

    edge_kernel<<<2368, 256>>>(edges, Wattn, hidden, out, n_edge);

    final_kernel<<<(n_node + 63) / 64, 256>>>(Wh, out, n_node);
}

// round 4
// speedup vs baseline: 2.1301x; 1.2128x over previous
#include <cuda_runtime.h>
#include <cuda_bf16.h>
#include <math.h>

// ---------------------------------------------------------------------------
// GNNModel: hyperbolic GNN message passing (c = 1e-6)
// ---------------------------------------------------------------------------

#define MAX_NODE 100000
#define MAX_VOCAB 512
#define MAX_B 256
#define DD 64
#define TILES 4

// attention tables in bf16 (only feed sigmoid(relu(.)@Wattn) — error << 1e-3)
__device__ __align__(16) __nv_bfloat16 g_hs_projh [MAX_NODE * DD];
__device__ __align__(16) __nv_bfloat16 g_rel_projh[MAX_VOCAB * DD];
__device__ __align__(16) __nv_bfloat16 g_qr_projh [MAX_B * DD];
__device__ float2 g_hs_sc [MAX_NODE];        // (fac*ps, ||expmap0||^2 clamped)
__device__ float  g_hr_h  [MAX_VOCAB * DD];  // expmap0(rela_embed[r]) projected
__device__ float  g_hr_y2 [MAX_VOCAB];       // ||hr_h||^2

#define SC 1.0e-3f                    // sqrt(c), c = 1e-6
#define CC 1.0e-6f
#define MAXNORM (0.996f / SC)
#define MN2 (MAXNORM * MAXNORM)

// ---- packed f32x2 helpers ----
__device__ __forceinline__ unsigned long long pack2(float a, float b) {
    unsigned long long r;
    asm("mov.b64 %0, {%1, %2};" : "=l"(r)
        : "r"(__float_as_uint(a)), "r"(__float_as_uint(b)));
    return r;
}
__device__ __forceinline__ void unpack2(unsigned long long v, float& a, float& b) {
    unsigned lo, hi;
    asm("mov.b64 {%0, %1}, %2;" : "=r"(lo), "=r"(hi) : "l"(v));
    a = __uint_as_float(lo); b = __uint_as_float(hi);
}
__device__ __forceinline__ unsigned long long fma2(
    unsigned long long a, unsigned long long b, unsigned long long c) {
    unsigned long long d;
    asm("fma.rn.f32x2 %0, %1, %2, %3;" : "=l"(d) : "l"(a), "l"(b), "l"(c));
    return d;
}
// bf16 pair (packed in u32) -> two f32, pure ALU
__device__ __forceinline__ float bflo(unsigned u) { return __uint_as_float(u << 16); }
__device__ __forceinline__ float bfhi(unsigned u) { return __uint_as_float(u & 0xffff0000u); }

// artanh(z)/z as poly in z^2 (valid z^2 < 0.09, guarded fallback above)
__device__ __forceinline__ float artanh_ratio(float z2) {
    float f = fmaf(z2, fmaf(z2, fmaf(z2, fmaf(z2, 1.0f/9.0f, 1.0f/7.0f),
                                     0.2f), 1.0f/3.0f), 1.0f);
    if (z2 > 0.09f) {
        float z = sqrtf(z2);
        float zc = fminf(z, 1.0f - 1e-5f);
        f = 0.5f * (log1pf(zc) - log1pf(-zc)) / z;
    }
    return f;
}
// tanh(z)/z as poly in z^2 (valid z^2 < 0.09, guarded)
__device__ __forceinline__ float tanh_ratio(float z2) {
    float f = fmaf(z2, fmaf(z2, fmaf(z2, -17.0f/315.0f, 2.0f/15.0f),
                            -1.0f/3.0f), 1.0f);
    if (z2 > 0.09f) {
        float z = sqrtf(z2);
        f = tanhf(fminf(z, 15.0f)) / z;
    }
    return f;
}

// ---------------------------------------------------------------------------
// fused prep: one launch; blockIdx routes to mode.
// mode 0: nodes -> g_hs_projh (bf16), g_hs_sc, zero zout
// mode 1: rels  -> g_rel_projh (bf16), g_hr_h, g_hr_y2
// mode 2: qr    -> g_qr_projh (bf16)  (gather + bias)
// ---------------------------------------------------------------------------
__global__ __launch_bounds__(256) void prep_all(
    const float* __restrict__ Ws, const float* __restrict__ Wr,
    const float* __restrict__ Wqr, const float* __restrict__ hidden,
    const float* __restrict__ rela, const int* __restrict__ q_rel,
    const float* __restrict__ Wqr_b, float* __restrict__ zout,
    int n_node, int n_vocab, int nB, int nb0, int nb1)
{
    __shared__ float Wst[DD][DD + 1];
    __shared__ __align__(16) float hT[4][DD * 4];
    __shared__ float red2[4][2][4];

    int mode, bidx, n_rows;
    const float* W; const float* src;
    if ((int)blockIdx.x < nb0) {
        mode = 0; bidx = blockIdx.x; W = Ws; src = hidden; n_rows = n_node;
    } else if ((int)blockIdx.x < nb0 + nb1) {
        mode = 1; bidx = blockIdx.x - nb0; W = Wr; src = rela; n_rows = n_vocab;
    } else {
        mode = 2; bidx = blockIdx.x - nb0 - nb1; W = Wqr; src = rela; n_rows = nB;
    }

    int t = threadIdx.x;
    for (int i = t; i < DD * DD; i += 256) Wst[i & 63][i >> 6] = W[i];

    __nv_bfloat16* projh = (mode == 0) ? g_hs_projh :
                           (mode == 1) ? g_rel_projh : g_qr_projh;

    int g = t >> 6, j = t & 63, half = (t >> 5) & 1;
    float bias = (mode == 2) ? Wqr_b[j] : 0.0f;

    for (int tile = 0; tile < TILES; tile++) {
        int base = (bidx * TILES + tile) * 16;
        if (base >= n_rows) break;
        __syncthreads();
        for (int i = t; i < 1024; i += 256) {
            int r16 = i >> 6, k = i & 63;
            int row = base + r16;
            float v = 0.0f;
            if (row < n_rows) {
                int sr = (mode == 2) ? q_rel[row] : row;
                v = src[sr * DD + k];
            }
            hT[r16 >> 2][k * 4 + (r16 & 3)] = v;
        }
        __syncthreads();

        // per-row ||u||^2
        float4 hj = *(const float4*)&hT[g][j * 4];
        float s0 = hj.x * hj.x, s1 = hj.y * hj.y, s2 = hj.z * hj.z, s3 = hj.w * hj.w;
#pragma unroll
        for (int o = 16; o; o >>= 1) {
            s0 += __shfl_xor_sync(0xffffffffu, s0, o);
            s1 += __shfl_xor_sync(0xffffffffu, s1, o);
            s2 += __shfl_xor_sync(0xffffffffu, s2, o);
            s3 += __shfl_xor_sync(0xffffffffu, s3, o);
        }
        if ((t & 31) == 0) {
            red2[g][half][0] = s0; red2[g][half][1] = s1;
            red2[g][half][2] = s2; red2[g][half][3] = s3;
        }
        __syncthreads();
        float nsq[4];
#pragma unroll
        for (int r = 0; r < 4; r++) nsq[r] = red2[g][0][r] + red2[g][1][r];

        // matvec via packed f32x2
        unsigned long long acc01 = pack2(bias, bias), acc23 = pack2(bias, bias);
#pragma unroll
        for (int k = 0; k < DD; k++) {
            float w = Wst[k][j];
            unsigned long long ww = pack2(w, w);
            ulonglong2 hh = *(const ulonglong2*)&hT[g][k * 4];
            acc01 = fma2(ww, hh.x, acc01);
            acc23 = fma2(ww, hh.y, acc23);
        }
        float acc[4];
        unpack2(acc01, acc[0], acc[1]);
        unpack2(acc23, acc[2], acc[3]);
        float hv[4] = {hj.x, hj.y, hj.z, hj.w};

#pragma unroll
        for (int r = 0; r < 4; r++) {
            int row = base + g * 4 + r;
            if (row >= n_rows) continue;
            projh[row * DD + j] = __float2bfloat16(acc[r]);
            if (mode != 2) {
                float z2  = CC * nsq[r];
                float fac = tanh_ratio(z2);
                float rn2 = fac * fac * nsq[r];
                float ps  = 1.0f;
                if (rn2 > MN2) ps = MAXNORM * rsqrtf(rn2);
                float fp  = fac * ps;
                float x2c = fminf(rn2, MN2);
                if (mode == 1) {
                    g_hr_h[row * DD + j] = fp * hv[r];
                    if (j == 0) g_hr_y2[row] = x2c;
                } else {
                    if (j == 0) g_hs_sc[row] = make_float2(fp, x2c);
                }
            }
            if (mode == 0) zout[row * DD + j] = 0.0f;
        }
    }
}

// ---------------------------------------------------------------------------
// edge kernel: 16 lanes per group, 2 consecutive edges per group per iter.
// bf16 attention tables; x reconstructed as fac_s * hidden[sub].
// ---------------------------------------------------------------------------
struct EdgeVals {
    int sub, obj;
    float s, pd;
    float4 hx, y;
    float x2, y2, fac;
};

__device__ __forceinline__ void edge_load(
    const int* __restrict__ edges, const float* __restrict__ hidden,
    float4 wa, int l, int e, EdgeVals& v)
{
    const int2* ep = (const int2*)edges + (long)e * 3;
    int2 w0 = __ldg(ep), w1 = __ldg(ep + 1), w2 = __ldg(ep + 2);
    int r_idx = w0.x, rel = w1.x;
    v.sub = w2.x; v.obj = w2.y;

    uint2 pb = __ldg((const uint2*)g_hs_projh  + v.sub * 16 + l);
    uint2 rb = __ldg((const uint2*)g_rel_projh + rel   * 16 + l);
    uint2 qb = __ldg((const uint2*)g_qr_projh  + r_idx * 16 + l);

    float t0 = bflo(pb.x) + bflo(rb.x) + bflo(qb.x);
    float t1 = bfhi(pb.x) + bfhi(rb.x) + bfhi(qb.x);
    float t2 = bflo(pb.y) + bflo(rb.y) + bflo(qb.y);
    float t3 = bfhi(pb.y) + bfhi(rb.y) + bfhi(qb.y);

    float s =      fmaxf(t0, 0.0f) * wa.x;
    s = fmaf(fmaxf(t1, 0.0f), wa.y, s);
    s = fmaf(fmaxf(t2, 0.0f), wa.z, s);
    s = fmaf(fmaxf(t3, 0.0f), wa.w, s);
    v.s = s;

    v.hx = __ldg((const float4*)hidden + v.sub * 16 + l);
    v.y  = __ldg((const float4*)g_hr_h + rel   * 16 + l);
    float pd = v.hx.x * v.y.x;
    pd = fmaf(v.hx.y, v.y.y, pd);
    pd = fmaf(v.hx.z, v.y.z, pd);
    pd = fmaf(v.hx.w, v.y.w, pd);
    v.pd = pd;

    float2 scs = __ldg(&g_hs_sc[v.sub]);
    v.fac = scs.x; v.x2 = scs.y;
    v.y2  = __ldg(&g_hr_y2[rel]);
}

__device__ __forceinline__ void edge_finish(
    const EdgeVals& v, float* __restrict__ out, int l)
{
    float xy = v.fac * v.pd;
    float alpha = __fdividef(1.0f, 1.0f + __expf(-v.s));

    float A   = 1.0f + 2.0f * CC * xy + CC * v.y2;
    float B   = 1.0f - CC * v.x2;
    float den = fmaxf(1.0f + 2.0f * CC * xy + CC * CC * v.x2 * v.y2, 1e-15f);
    float inv = __fdividef(1.0f, den);
    float mm = fmaf(A * A, v.x2, fmaf(2.0f * A * B, xy, B * B * v.y2)) * inv * inv;
    mm = fmaxf(mm, 0.0f);
    float ps = 1.0f;
    if (mm > MN2) ps = MAXNORM * rsqrtf(mm);
    float z2 = CC * fminf(mm, MN2);
    float f  = artanh_ratio(z2);

    float sc = alpha * f * ps * inv;
    float sA = A * sc * v.fac;
    float sB = B * sc;

    float g0 = fmaf(sA, v.hx.x, sB * v.y.x);
    float g1 = fmaf(sA, v.hx.y, sB * v.y.y);
    float g2 = fmaf(sA, v.hx.z, sB * v.y.z);
    float g3 = fmaf(sA, v.hx.w, sB * v.y.w);

    float* dst = out + (long)v.obj * DD + l * 4;
    asm volatile("red.global.add.v4.f32 [%0], {%1,%2,%3,%4};"
                 :: "l"(dst), "f"(g0), "f"(g1), "f"(g2), "f"(g3) : "memory");
}

__global__ __launch_bounds__(256) void edge_kernel(
    const int* __restrict__ edges, const float* __restrict__ Wattn,
    const float* __restrict__ hidden, float* __restrict__ out, int n_edge)
{
    int l = threadIdx.x & 15;
    float4 wa = __ldg((const float4*)Wattn + l);
    int group  = (blockIdx.x * blockDim.x + threadIdx.x) >> 4;
    int stride = (gridDim.x * blockDim.x) >> 4;
    int npair  = (n_edge + 1) >> 1;

    for (int p = group; p < npair; p += stride) {
        int e0 = p * 2;
        bool has1 = (e0 + 1) < n_edge;

        EdgeVals v0, v1;
        edge_load(edges, hidden, wa, l, e0, v0);
        if (has1) edge_load(edges, hidden, wa, l, e0 + 1, v1);
        else { v1.s = 0; v1.pd = 0; }

        float a = v0.s, b = v0.pd, c2 = v1.s, d = v1.pd;
#pragma unroll
        for (int o = 8; o; o >>= 1) {
            a  += __shfl_xor_sync(0xffffffffu, a,  o);
            b  += __shfl_xor_sync(0xffffffffu, b,  o);
            c2 += __shfl_xor_sync(0xffffffffu, c2, o);
            d  += __shfl_xor_sync(0xffffffffu, d,  o);
        }
        v0.s = a; v0.pd = b; v1.s = c2; v1.pd = d;

        edge_finish(v0, out, l);
        if (has1) edge_finish(v1, out, l);
    }
}

// ---------------------------------------------------------------------------
// final: out[n] = logmap0(relu(expmap0(Wh @ agg[n])))  (in-place)
// ---------------------------------------------------------------------------
__global__ __launch_bounds__(256) void final_kernel(
    const float* __restrict__ Wh, float* __restrict__ out, int n_node)
{
    __shared__ float Wst[DD][DD + 1];
    __shared__ __align__(16) float hT[4][DD * 4];
    __shared__ float red2[4][2][4];

    int t = threadIdx.x;
    for (int i = t; i < DD * DD; i += 256) Wst[i & 63][i >> 6] = Wh[i];

    int g = t >> 6, j = t & 63, half = (t >> 5) & 1;

    for (int tile = 0; tile < TILES; tile++) {
        int base = (blockIdx.x * TILES + tile) * 16;
        if (base >= n_node) break;
        __syncthreads();
        for (int i = t; i < 1024; i += 256) {
            int r16 = i >> 6, k = i & 63;
            int row = base + r16;
            hT[r16 >> 2][k * 4 + (r16 & 3)] = (row < n_node) ? out[row * DD + k] : 0.0f;
        }
        __syncthreads();

        unsigned long long acc01 = 0ull, acc23 = 0ull;
#pragma unroll
        for (int k = 0; k < DD; k++) {
            float w = Wst[k][j];
            unsigned long long ww = pack2(w, w);
            ulonglong2 hh = *(const ulonglong2*)&hT[g][k * 4];
            acc01 = fma2(ww, hh.x, acc01);
            acc23 = fma2(ww, hh.y, acc23);
        }
        float acc[4];
        unpack2(acc01, acc[0], acc[1]);
        unpack2(acc23, acc[2], acc[3]);

        float s0 = acc[0]*acc[0], s1 = acc[1]*acc[1], s2 = acc[2]*acc[2], s3 = acc[3]*acc[3];
#pragma unroll
        for (int o = 16; o; o >>= 1) {
            s0 += __shfl_xor_sync(0xffffffffu, s0, o);
            s1 += __shfl_xor_sync(0xffffffffu, s1, o);
            s2 += __shfl_xor_sync(0xffffffffu, s2, o);
            s3 += __shfl_xor_sync(0xffffffffu, s3, o);
        }
        if ((t & 31) == 0) {
            red2[g][half][0] = s0; red2[g][half][1] = s1;
            red2[g][half][2] = s2; red2[g][half][3] = s3;
        }
        __syncthreads();
        float av[4];
#pragma unroll
        for (int r = 0; r < 4; r++) {
            float nv2 = red2[g][0][r] + red2[g][1][r];
            float z2  = CC * nv2;
            float fac = tanh_ratio(z2);
            float rn2 = fac * fac * nv2;
            float ps  = 1.0f;
            if (rn2 > MN2) ps = MAXNORM * rsqrtf(rn2);
            av[r] = fmaxf(acc[r] * fac * ps, 0.0f);
        }
        __syncthreads();

        s0 = av[0]*av[0]; s1 = av[1]*av[1]; s2 = av[2]*av[2]; s3 = av[3]*av[3];
#pragma unroll
        for (int o = 16; o; o >>= 1) {
            s0 += __shfl_xor_sync(0xffffffffu, s0, o);
            s1 += __shfl_xor_sync(0xffffffffu, s1, o);
            s2 += __shfl_xor_sync(0xffffffffu, s2, o);
            s3 += __shfl_xor_sync(0xffffffffu, s3, o);
        }
        if ((t & 31) == 0) {
            red2[g][half][0] = s0; red2[g][half][1] = s1;
            red2[g][half][2] = s2; red2[g][half][3] = s3;
        }
        __syncthreads();
#pragma unroll
        for (int r = 0; r < 4; r++) {
            int row = base + g * 4 + r;
            if (row >= n_node) continue;
            float na2 = red2[g][0][r] + red2[g][1][r];
            float z2  = CC * na2;
            float gg  = artanh_ratio(z2);
            out[row * DD + j] = av[r] * gg;
        }
    }
}

// ---------------------------------------------------------------------------
extern "C" void kernel_launch(void* const* d_in, const int* in_sizes, int n_in,
                              void* d_out, int out_size)
{
    const float* hidden = (const float*)d_in[0];
    const int*   q_rel  = (const int*)  d_in[1];
    const int*   edges  = (const int*)  d_in[2];
    const float* rela   = (const float*)d_in[3];
    const float* Ws     = (const float*)d_in[4];
    const float* Wr     = (const float*)d_in[5];
    const float* Wqr    = (const float*)d_in[6];
    const float* Wqr_b  = (const float*)d_in[7];
    const float* Wattn  = (const float*)d_in[8];
    const float* Wh     = (const float*)d_in[9];
    float* out = (float*)d_out;

    int n_node  = in_sizes[0] / DD;
    int Bn      = in_sizes[1];
    int n_edge  = in_sizes[2] / 6;
    int n_vocab = in_sizes[3] / DD;

    int nb0 = (n_node  + 63) / 64;
    int nb1 = (n_vocab + 63) / 64;
    int nb2 = (Bn      + 63) / 64;

    prep_all<<<nb0 + nb1 + nb2, 256>>>(Ws, Wr, Wqr, hidden, rela, q_rel, Wqr_b,
                                       out, n_node, n_vocab, Bn, nb0, nb1);

    edge_kernel<<<2368, 256>>>(edges, Wattn, hidden, out, n_edge);

    final_kernel<<<(n_node + 63) / 64, 256>>>(Wh, out, n_node);
}

// round 5
// speedup vs baseline: 2.1899x; 1.0281x over previous
#include <cuda_runtime.h>
#include <cuda_bf16.h>
#include <math.h>

// ---------------------------------------------------------------------------
// GNNModel: hyperbolic GNN message passing (c = 1e-6)
// ---------------------------------------------------------------------------

#define MAX_NODE 100000
#define MAX_VOCAB 512
#define MAX_B 256
#define DD 64
#define TILES 4

// attention tables in bf16 (only feed sigmoid(relu(.)@Wattn) — error << 1e-3)
__device__ __align__(16) __nv_bfloat16 g_hs_projh [MAX_NODE * DD];
__device__ __align__(16) __nv_bfloat16 g_rel_projh[MAX_VOCAB * DD];
__device__ __align__(16) __nv_bfloat16 g_qr_projh [MAX_B * DD];
__device__ float2 g_hs_sc [MAX_NODE];        // (fac*ps, ||expmap0||^2 clamped)
__device__ float  g_hr_h  [MAX_VOCAB * DD];  // expmap0(rela_embed[r]) projected
__device__ float  g_hr_y2 [MAX_VOCAB];       // ||hr_h||^2

#define SC 1.0e-3f                    // sqrt(c), c = 1e-6
#define CC 1.0e-6f
#define MAXNORM (0.996f / SC)
#define MN2 (MAXNORM * MAXNORM)

// ---- packed f32x2 helpers ----
__device__ __forceinline__ unsigned long long pack2(float a, float b) {
    unsigned long long r;
    asm("mov.b64 %0, {%1, %2};" : "=l"(r)
        : "r"(__float_as_uint(a)), "r"(__float_as_uint(b)));
    return r;
}
__device__ __forceinline__ void unpack2(unsigned long long v, float& a, float& b) {
    unsigned lo, hi;
    asm("mov.b64 {%0, %1}, %2;" : "=r"(lo), "=r"(hi) : "l"(v));
    a = __uint_as_float(lo); b = __uint_as_float(hi);
}
__device__ __forceinline__ unsigned long long fma2(
    unsigned long long a, unsigned long long b, unsigned long long c) {
    unsigned long long d;
    asm("fma.rn.f32x2 %0, %1, %2, %3;" : "=l"(d) : "l"(a), "l"(b), "l"(c));
    return d;
}
// bf16 pair (packed in u32) -> two f32, pure ALU
__device__ __forceinline__ float bflo(unsigned u) { return __uint_as_float(u << 16); }
__device__ __forceinline__ float bfhi(unsigned u) { return __uint_as_float(u & 0xffff0000u); }

// artanh(z)/z as poly in z^2 (valid z^2 < 0.09, guarded fallback above)
__device__ __forceinline__ float artanh_ratio(float z2) {
    float f = fmaf(z2, fmaf(z2, fmaf(z2, fmaf(z2, 1.0f/9.0f, 1.0f/7.0f),
                                     0.2f), 1.0f/3.0f), 1.0f);
    if (z2 > 0.09f) {
        float z = sqrtf(z2);
        float zc = fminf(z, 1.0f - 1e-5f);
        f = 0.5f * (log1pf(zc) - log1pf(-zc)) / z;
    }
    return f;
}
// tanh(z)/z as poly in z^2 (valid z^2 < 0.09, guarded)
__device__ __forceinline__ float tanh_ratio(float z2) {
    float f = fmaf(z2, fmaf(z2, fmaf(z2, -17.0f/315.0f, 2.0f/15.0f),
                            -1.0f/3.0f), 1.0f);
    if (z2 > 0.09f) {
        float z = sqrtf(z2);
        f = tanhf(fminf(z, 15.0f)) / z;
    }
    return f;
}

// ---------------------------------------------------------------------------
// fused prep: one launch; blockIdx routes to mode.
// mode 0: nodes -> g_hs_projh (bf16), g_hs_sc, zero zout
// mode 1: rels  -> g_rel_projh (bf16), g_hr_h, g_hr_y2
// mode 2: qr    -> g_qr_projh (bf16)  (gather + bias)
// Double-buffered staging; norms folded into matvec loop (no pre-reduction).
// ---------------------------------------------------------------------------
__global__ __launch_bounds__(256) void prep_all(
    const float* __restrict__ Ws, const float* __restrict__ Wr,
    const float* __restrict__ Wqr, const float* __restrict__ hidden,
    const float* __restrict__ rela, const int* __restrict__ q_rel,
    const float* __restrict__ Wqr_b, float* __restrict__ zout,
    int n_node, int n_vocab, int nB, int nb0, int nb1)
{
    __shared__ float Wst[DD][DD + 1];
    __shared__ __align__(16) float hT[4][DD * 4];

    int mode, bidx, n_rows;
    const float* W; const float* src;
    if ((int)blockIdx.x < nb0) {
        mode = 0; bidx = blockIdx.x; W = Ws; src = hidden; n_rows = n_node;
    } else if ((int)blockIdx.x < nb0 + nb1) {
        mode = 1; bidx = blockIdx.x - nb0; W = Wr; src = rela; n_rows = n_vocab;
    } else {
        mode = 2; bidx = blockIdx.x - nb0 - nb1; W = Wqr; src = rela; n_rows = nB;
    }

    int t = threadIdx.x;
    for (int i = t; i < DD * DD; i += 256) Wst[i & 63][i >> 6] = W[i];

    __nv_bfloat16* projh = (mode == 0) ? g_hs_projh :
                           (mode == 1) ? g_rel_projh : g_qr_projh;

    int g = t >> 6, j = t & 63;
    float bias = (mode == 2) ? Wqr_b[j] : 0.0f;

    float pf[4];
    // prefetch tile 0: thread loads rows base+g+4u, column j
    {
        int base = (bidx * TILES) * 16;
#pragma unroll
        for (int u = 0; u < 4; u++) {
            int row = base + g + 4 * u;
            float v = 0.0f;
            if (row < n_rows) {
                int sr = (mode == 2) ? __ldg(&q_rel[row]) : row;
                v = __ldg(&src[sr * DD + j]);
            }
            pf[u] = v;
        }
    }

    for (int tile = 0; tile < TILES; tile++) {
        int base = (bidx * TILES + tile) * 16;
        if (base >= n_rows) break;

        __syncthreads();                 // hT free from previous compute
#pragma unroll
        for (int u = 0; u < 4; u++) hT[u][j * 4 + g] = pf[u];
        __syncthreads();

        // prefetch next tile while computing
        int nbase = base + 16;
        if (tile + 1 < TILES && nbase < n_rows) {
#pragma unroll
            for (int u = 0; u < 4; u++) {
                int row = nbase + g + 4 * u;
                float v = 0.0f;
                if (row < n_rows) {
                    int sr = (mode == 2) ? __ldg(&q_rel[row]) : row;
                    v = __ldg(&src[sr * DD + j]);
                }
                pf[u] = v;
            }
        }

        // matvec + norms via packed f32x2 (norms redundantly per-thread)
        unsigned long long acc01 = pack2(bias, bias), acc23 = pack2(bias, bias);
        unsigned long long nn01 = 0ull, nn23 = 0ull;
#pragma unroll
        for (int k = 0; k < DD; k++) {
            float w = Wst[k][j];
            unsigned long long ww = pack2(w, w);
            ulonglong2 hh = *(const ulonglong2*)&hT[g][k * 4];
            acc01 = fma2(ww, hh.x, acc01);
            acc23 = fma2(ww, hh.y, acc23);
            nn01  = fma2(hh.x, hh.x, nn01);
            nn23  = fma2(hh.y, hh.y, nn23);
        }
        float acc[4], nsq[4];
        unpack2(acc01, acc[0], acc[1]);
        unpack2(acc23, acc[2], acc[3]);
        unpack2(nn01,  nsq[0], nsq[1]);
        unpack2(nn23,  nsq[2], nsq[3]);

        float4 hj = *(const float4*)&hT[g][j * 4];
        float hv[4] = {hj.x, hj.y, hj.z, hj.w};

#pragma unroll
        for (int r = 0; r < 4; r++) {
            int row = base + g * 4 + r;
            if (row >= n_rows) continue;
            projh[row * DD + j] = __float2bfloat16(acc[r]);
            if (mode != 2) {
                float z2  = CC * nsq[r];
                float fac = tanh_ratio(z2);
                float rn2 = fac * fac * nsq[r];
                float ps  = 1.0f;
                if (rn2 > MN2) ps = MAXNORM * rsqrtf(rn2);
                float fp  = fac * ps;
                float x2c = fminf(rn2, MN2);
                if (mode == 1) {
                    g_hr_h[row * DD + j] = fp * hv[r];
                    if (j == 0) g_hr_y2[row] = x2c;
                } else {
                    if (j == 0) g_hs_sc[row] = make_float2(fp, x2c);
                }
            }
            if (mode == 0) zout[row * DD + j] = 0.0f;
        }
    }
}

// ---------------------------------------------------------------------------
// edge kernel: 16 lanes per group, 2 consecutive edges per group per iter,
// edge indices software-pipelined one iteration ahead.
// ---------------------------------------------------------------------------
struct EdgeVals {
    int sub, obj;
    float s, pd;
    float4 hx, y;
    float x2, y2, fac;
};

__device__ __forceinline__ void edge_load(
    const float* __restrict__ hidden, float4 wa, int l,
    int r_idx, int rel, int sub, int obj, EdgeVals& v)
{
    v.sub = sub; v.obj = obj;

    uint2 pb = __ldg((const uint2*)g_hs_projh  + sub   * 16 + l);
    uint2 rb = __ldg((const uint2*)g_rel_projh + rel   * 16 + l);
    uint2 qb = __ldg((const uint2*)g_qr_projh  + r_idx * 16 + l);

    float t0 = bflo(pb.x) + bflo(rb.x) + bflo(qb.x);
    float t1 = bfhi(pb.x) + bfhi(rb.x) + bfhi(qb.x);
    float t2 = bflo(pb.y) + bflo(rb.y) + bflo(qb.y);
    float t3 = bfhi(pb.y) + bfhi(rb.y) + bfhi(qb.y);

    float s =      fmaxf(t0, 0.0f) * wa.x;
    s = fmaf(fmaxf(t1, 0.0f), wa.y, s);
    s = fmaf(fmaxf(t2, 0.0f), wa.z, s);
    s = fmaf(fmaxf(t3, 0.0f), wa.w, s);
    v.s = s;

    v.hx = __ldg((const float4*)hidden + sub * 16 + l);
    v.y  = __ldg((const float4*)g_hr_h + rel * 16 + l);
    float pd = v.hx.x * v.y.x;
    pd = fmaf(v.hx.y, v.y.y, pd);
    pd = fmaf(v.hx.z, v.y.z, pd);
    pd = fmaf(v.hx.w, v.y.w, pd);
    v.pd = pd;

    float2 scs = __ldg(&g_hs_sc[sub]);
    v.fac = scs.x; v.x2 = scs.y;
    v.y2  = __ldg(&g_hr_y2[rel]);
}

__device__ __forceinline__ void edge_finish(
    const EdgeVals& v, float* __restrict__ out, int l)
{
    float xy = v.fac * v.pd;
    float alpha = __fdividef(1.0f, 1.0f + __expf(-v.s));

    float A   = 1.0f + 2.0f * CC * xy + CC * v.y2;
    float B   = 1.0f - CC * v.x2;
    float den = fmaxf(1.0f + 2.0f * CC * xy + CC * CC * v.x2 * v.y2, 1e-15f);
    float inv = __fdividef(1.0f, den);
    float mm = fmaf(A * A, v.x2, fmaf(2.0f * A * B, xy, B * B * v.y2)) * inv * inv;
    mm = fmaxf(mm, 0.0f);
    float ps = 1.0f;
    if (mm > MN2) ps = MAXNORM * rsqrtf(mm);
    float z2 = CC * fminf(mm, MN2);
    float f  = artanh_ratio(z2);

    float sc = alpha * f * ps * inv;
    float sA = A * sc * v.fac;
    float sB = B * sc;

    float g0 = fmaf(sA, v.hx.x, sB * v.y.x);
    float g1 = fmaf(sA, v.hx.y, sB * v.y.y);
    float g2 = fmaf(sA, v.hx.z, sB * v.y.z);
    float g3 = fmaf(sA, v.hx.w, sB * v.y.w);

    float* dst = out + (long)v.obj * DD + l * 4;
    asm volatile("red.global.add.v4.f32 [%0], {%1,%2,%3,%4};"
                 :: "l"(dst), "f"(g0), "f"(g1), "f"(g2), "f"(g3) : "memory");
}

__global__ __launch_bounds__(256) void edge_kernel(
    const int* __restrict__ edges, const float* __restrict__ Wattn,
    const float* __restrict__ hidden, float* __restrict__ out, int n_edge)
{
    int l = threadIdx.x & 15;
    float4 wa = __ldg((const float4*)Wattn + l);
    int group  = (blockIdx.x * blockDim.x + threadIdx.x) >> 4;
    int stride = (gridDim.x * blockDim.x) >> 4;
    int npair  = (n_edge + 1) >> 1;

    int p = group;
    int2 c0a, c0b, c0c, c1a, c1b, c1c;
    if (p < npair) {
        const int2* e0 = (const int2*)edges + (long)(p * 2) * 3;
        c0a = __ldg(e0); c0b = __ldg(e0 + 1); c0c = __ldg(e0 + 2);
        if (p * 2 + 1 < n_edge) {
            c1a = __ldg(e0 + 3); c1b = __ldg(e0 + 4); c1c = __ldg(e0 + 5);
        } else { c1a = c0a; c1b = c0b; c1c = c0c; }
    }

    while (p < npair) {
        int2 i0a = c0a, i0b = c0b, i0c = c0c;
        int2 i1a = c1a, i1b = c1b, i1c = c1c;
        bool has1 = (p * 2 + 1) < n_edge;

        int pn = p + stride;
        if (pn < npair) {
            const int2* e0 = (const int2*)edges + (long)(pn * 2) * 3;
            c0a = __ldg(e0); c0b = __ldg(e0 + 1); c0c = __ldg(e0 + 2);
            if (pn * 2 + 1 < n_edge) {
                c1a = __ldg(e0 + 3); c1b = __ldg(e0 + 4); c1c = __ldg(e0 + 5);
            }
        }

        EdgeVals v0, v1;
        edge_load(hidden, wa, l, i0a.x, i0b.x, i0c.x, i0c.y, v0);
        if (has1) edge_load(hidden, wa, l, i1a.x, i1b.x, i1c.x, i1c.y, v1);
        else { v1.s = 0; v1.pd = 0; }

        float a = v0.s, b = v0.pd, c2 = v1.s, d = v1.pd;
#pragma unroll
        for (int o = 8; o; o >>= 1) {
            a  += __shfl_xor_sync(0xffffffffu, a,  o);
            b  += __shfl_xor_sync(0xffffffffu, b,  o);
            c2 += __shfl_xor_sync(0xffffffffu, c2, o);
            d  += __shfl_xor_sync(0xffffffffu, d,  o);
        }
        v0.s = a; v0.pd = b; v1.s = c2; v1.pd = d;

        edge_finish(v0, out, l);
        if (has1) edge_finish(v1, out, l);

        p = pn;
    }
}

// ---------------------------------------------------------------------------
// final: out[n] = logmap0(relu(expmap0(Wh @ agg[n])))  (in-place)
// Single fused reduction: ||av||^2 = (fac*ps)^2 * sum(max(acc,0)^2).
// ---------------------------------------------------------------------------
__global__ __launch_bounds__(256) void final_kernel(
    const float* __restrict__ Wh, float* __restrict__ out, int n_node)
{
    __shared__ float Wst[DD][DD + 1];
    __shared__ __align__(16) float hT[4][DD * 4];
    __shared__ float red2[4][2][8];

    int t = threadIdx.x;
    for (int i = t; i < DD * DD; i += 256) Wst[i & 63][i >> 6] = Wh[i];

    int g = t >> 6, j = t & 63, half = (t >> 5) & 1;

    float pf[4];
    {
        int base = (blockIdx.x * TILES) * 16;
#pragma unroll
        for (int u = 0; u < 4; u++) {
            int row = base + g + 4 * u;
            pf[u] = (row < n_node) ? __ldg(&out[row * DD + j]) : 0.0f;
        }
    }

    for (int tile = 0; tile < TILES; tile++) {
        int base = (blockIdx.x * TILES + tile) * 16;
        if (base >= n_node) break;

        __syncthreads();
#pragma unroll
        for (int u = 0; u < 4; u++) hT[u][j * 4 + g] = pf[u];
        __syncthreads();

        int nbase = base + 16;
        if (tile + 1 < TILES && nbase < n_node) {
#pragma unroll
            for (int u = 0; u < 4; u++) {
                int row = nbase + g + 4 * u;
                pf[u] = (row < n_node) ? __ldg(&out[row * DD + j]) : 0.0f;
            }
        }

        unsigned long long acc01 = 0ull, acc23 = 0ull;
#pragma unroll
        for (int k = 0; k < DD; k++) {
            float w = Wst[k][j];
            unsigned long long ww = pack2(w, w);
            ulonglong2 hh = *(const ulonglong2*)&hT[g][k * 4];
            acc01 = fma2(ww, hh.x, acc01);
            acc23 = fma2(ww, hh.y, acc23);
        }
        float acc[4];
        unpack2(acc01, acc[0], acc[1]);
        unpack2(acc23, acc[2], acc[3]);

        // fused reduction: sum acc^2 and sum max(acc,0)^2 for 4 rows
        float sa[4], sp[4];
#pragma unroll
        for (int r = 0; r < 4; r++) {
            float ap = fmaxf(acc[r], 0.0f);
            sa[r] = acc[r] * acc[r];
            sp[r] = ap * ap;
        }
#pragma unroll
        for (int o = 16; o; o >>= 1) {
#pragma unroll
            for (int r = 0; r < 4; r++) {
                sa[r] += __shfl_xor_sync(0xffffffffu, sa[r], o);
                sp[r] += __shfl_xor_sync(0xffffffffu, sp[r], o);
            }
        }
        if ((t & 31) == 0) {
#pragma unroll
            for (int r = 0; r < 4; r++) {
                red2[g][half][r]     = sa[r];
                red2[g][half][4 + r] = sp[r];
            }
        }
        __syncthreads();

#pragma unroll
        for (int r = 0; r < 4; r++) {
            int row = base + g * 4 + r;
            if (row >= n_node) continue;
            float nv2 = red2[g][0][r]     + red2[g][1][r];
            float sp2 = red2[g][0][4 + r] + red2[g][1][4 + r];
            float z2  = CC * nv2;
            float fac = tanh_ratio(z2);
            float rn2 = fac * fac * nv2;
            float ps  = 1.0f;
            if (rn2 > MN2) ps = MAXNORM * rsqrtf(rn2);
            float fp  = fac * ps;
            float na2 = fp * fp * sp2;               // ||relu(expmap0)||^2
            float gg  = artanh_ratio(CC * na2);
            out[row * DD + j] = fp * fmaxf(acc[r], 0.0f) * gg;
        }
    }
}

// ---------------------------------------------------------------------------
extern "C" void kernel_launch(void* const* d_in, const int* in_sizes, int n_in,
                              void* d_out, int out_size)
{
    const float* hidden = (const float*)d_in[0];
    const int*   q_rel  = (const int*)  d_in[1];
    const int*   edges  = (const int*)  d_in[2];
    const float* rela   = (const float*)d_in[3];
    const float* Ws     = (const float*)d_in[4];
    const float* Wr     = (const float*)d_in[5];
    const float* Wqr    = (const float*)d_in[6];
    const float* Wqr_b  = (const float*)d_in[7];
    const float* Wattn  = (const float*)d_in[8];
    const float* Wh     = (const float*)d_in[9];
    float* out = (float*)d_out;

    int n_node  = in_sizes[0] / DD;
    int Bn      = in_sizes[1];
    int n_edge  = in_sizes[2] / 6;
    int n_vocab = in_sizes[3] / DD;

    int nb0 = (n_node  + 63) / 64;
    int nb1 = (n_vocab + 63) / 64;
    int nb2 = (Bn      + 63) / 64;

    prep_all<<<nb0 + nb1 + nb2, 256>>>(Ws, Wr, Wqr, hidden, rela, q_rel, Wqr_b,
                                       out, n_node, n_vocab, Bn, nb0, nb1);

    edge_kernel<<<2368, 256>>>(edges, Wattn, hidden, out, n_edge);

    final_kernel<<<(n_node + 63) / 64, 256>>>(Wh, out, n_node);
}

// round 6
// speedup vs baseline: 2.2505x; 1.0277x over previous
#include <cuda_runtime.h>
#include <cuda_bf16.h>
#include <math.h>

// ---------------------------------------------------------------------------
// GNNModel: hyperbolic GNN message passing (c = 1e-6)
// ---------------------------------------------------------------------------

#define MAX_NODE 100000
#define MAX_VOCAB 512
#define MAX_B 256
#define DD 64
#define TILES 4

// attention tables in bf16 (only feed sigmoid(relu(.)@Wattn) — error << 1e-3)
__device__ __align__(16) __nv_bfloat16 g_hs_projh [MAX_NODE * DD];
__device__ __align__(16) __nv_bfloat16 g_rel_projh[MAX_VOCAB * DD];
__device__ __align__(16) __nv_bfloat16 g_qr_projh [MAX_B * DD];
__device__ float2 g_hs_sc [MAX_NODE];        // (fac*ps, ||expmap0||^2 clamped)
__device__ float  g_hr_h  [MAX_VOCAB * DD];  // expmap0(rela_embed[r]) projected
__device__ float  g_hr_y2 [MAX_VOCAB];       // ||hr_h||^2

#define SC 1.0e-3f                    // sqrt(c), c = 1e-6
#define CC 1.0e-6f
#define MAXNORM (0.996f / SC)
#define MN2 (MAXNORM * MAXNORM)

// ---- packed f32x2 helpers ----
__device__ __forceinline__ unsigned long long pack2(float a, float b) {
    unsigned long long r;
    asm("mov.b64 %0, {%1, %2};" : "=l"(r)
        : "r"(__float_as_uint(a)), "r"(__float_as_uint(b)));
    return r;
}
__device__ __forceinline__ void unpack2(unsigned long long v, float& a, float& b) {
    unsigned lo, hi;
    asm("mov.b64 {%0, %1}, %2;" : "=r"(lo), "=r"(hi) : "l"(v));
    a = __uint_as_float(lo); b = __uint_as_float(hi);
}
__device__ __forceinline__ unsigned long long fma2(
    unsigned long long a, unsigned long long b, unsigned long long c) {
    unsigned long long d;
    asm("fma.rn.f32x2 %0, %1, %2, %3;" : "=l"(d) : "l"(a), "l"(b), "l"(c));
    return d;
}
// bf16 pair (packed in u32) -> two f32, pure ALU
__device__ __forceinline__ float bflo(unsigned u) { return __uint_as_float(u << 16); }
__device__ __forceinline__ float bfhi(unsigned u) { return __uint_as_float(u & 0xffff0000u); }

// artanh(z)/z as poly in z^2 (valid z^2 < 0.09, guarded fallback above)
__device__ __forceinline__ float artanh_ratio(float z2) {
    float f = fmaf(z2, fmaf(z2, fmaf(z2, fmaf(z2, 1.0f/9.0f, 1.0f/7.0f),
                                     0.2f), 1.0f/3.0f), 1.0f);
    if (z2 > 0.09f) {
        float z = sqrtf(z2);
        float zc = fminf(z, 1.0f - 1e-5f);
        f = 0.5f * (log1pf(zc) - log1pf(-zc)) / z;
    }
    return f;
}
// tanh(z)/z as poly in z^2 (valid z^2 < 0.09, guarded)
__device__ __forceinline__ float tanh_ratio(float z2) {
    float f = fmaf(z2, fmaf(z2, fmaf(z2, -17.0f/315.0f, 2.0f/15.0f),
                            -1.0f/3.0f), 1.0f);
    if (z2 > 0.09f) {
        float z = sqrtf(z2);
        f = tanhf(fminf(z, 15.0f)) / z;
    }
    return f;
}

// ---------------------------------------------------------------------------
// fused prep: one launch; blockIdx routes to mode. Double-buffered staging:
// one barrier per tile, LDG latency hidden under the matvec.
// ---------------------------------------------------------------------------
__global__ __launch_bounds__(256) void prep_all(
    const float* __restrict__ Ws, const float* __restrict__ Wr,
    const float* __restrict__ Wqr, const float* __restrict__ hidden,
    const float* __restrict__ rela, const int* __restrict__ q_rel,
    const float* __restrict__ Wqr_b, float* __restrict__ zout,
    int n_node, int n_vocab, int nB, int nb0, int nb1)
{
    __shared__ float Wst[DD][DD + 1];
    __shared__ __align__(16) float hT[2][4][DD * 4];

    int mode, bidx, n_rows;
    const float* W; const float* src;
    if ((int)blockIdx.x < nb0) {
        mode = 0; bidx = blockIdx.x; W = Ws; src = hidden; n_rows = n_node;
    } else if ((int)blockIdx.x < nb0 + nb1) {
        mode = 1; bidx = blockIdx.x - nb0; W = Wr; src = rela; n_rows = n_vocab;
    } else {
        mode = 2; bidx = blockIdx.x - nb0 - nb1; W = Wqr; src = rela; n_rows = nB;
    }

    int t = threadIdx.x;
    for (int i = t; i < DD * DD; i += 256) Wst[i & 63][i >> 6] = W[i];

    __nv_bfloat16* projh = (mode == 0) ? g_hs_projh :
                           (mode == 1) ? g_rel_projh : g_qr_projh;

    int g = t >> 6, j = t & 63;
    float bias = (mode == 2) ? Wqr_b[j] : 0.0f;

    float pf[4];
    // prefetch tile 0: thread loads rows base+g+4u, column j
    {
        int base = (bidx * TILES) * 16;
#pragma unroll
        for (int u = 0; u < 4; u++) {
            int row = base + g + 4 * u;
            float v = 0.0f;
            if (row < n_rows) {
                int sr = (mode == 2) ? __ldg(&q_rel[row]) : row;
                v = __ldg(&src[sr * DD + j]);
            }
            pf[u] = v;
        }
    }

    int buf = 0;
    {
#pragma unroll
        for (int u = 0; u < 4; u++) hT[0][u][j * 4 + g] = pf[u];
        __syncthreads();
    }

    for (int tile = 0; tile < TILES; tile++) {
        int base = (bidx * TILES + tile) * 16;
        if (base >= n_rows) break;

        // prefetch next tile (regs) — latency hidden by compute below
        int nbase = base + 16;
        bool have_next = (tile + 1 < TILES) && (nbase < n_rows);
        if (have_next) {
#pragma unroll
            for (int u = 0; u < 4; u++) {
                int row = nbase + g + 4 * u;
                float v = 0.0f;
                if (row < n_rows) {
                    int sr = (mode == 2) ? __ldg(&q_rel[row]) : row;
                    v = __ldg(&src[sr * DD + j]);
                }
                pf[u] = v;
            }
        }

        // matvec + norms via packed f32x2 (norms redundantly per-thread)
        unsigned long long acc01 = pack2(bias, bias), acc23 = pack2(bias, bias);
        unsigned long long nn01 = 0ull, nn23 = 0ull;
#pragma unroll
        for (int k = 0; k < DD; k++) {
            float w = Wst[k][j];
            unsigned long long ww = pack2(w, w);
            ulonglong2 hh = *(const ulonglong2*)&hT[buf][g][k * 4];
            acc01 = fma2(ww, hh.x, acc01);
            acc23 = fma2(ww, hh.y, acc23);
            nn01  = fma2(hh.x, hh.x, nn01);
            nn23  = fma2(hh.y, hh.y, nn23);
        }
        float acc[4], nsq[4];
        unpack2(acc01, acc[0], acc[1]);
        unpack2(acc23, acc[2], acc[3]);
        unpack2(nn01,  nsq[0], nsq[1]);
        unpack2(nn23,  nsq[2], nsq[3]);

        float4 hj = *(const float4*)&hT[buf][g][j * 4];
        float hv[4] = {hj.x, hj.y, hj.z, hj.w};

#pragma unroll
        for (int r = 0; r < 4; r++) {
            int row = base + g * 4 + r;
            if (row >= n_rows) continue;
            projh[row * DD + j] = __float2bfloat16(acc[r]);
            if (mode != 2) {
                float z2  = CC * nsq[r];
                float fac = tanh_ratio(z2);
                float rn2 = fac * fac * nsq[r];
                float ps  = 1.0f;
                if (rn2 > MN2) ps = MAXNORM * rsqrtf(rn2);
                float fp  = fac * ps;
                float x2c = fminf(rn2, MN2);
                if (mode == 1) {
                    g_hr_h[row * DD + j] = fp * hv[r];
                    if (j == 0) g_hr_y2[row] = x2c;
                } else {
                    if (j == 0) g_hs_sc[row] = make_float2(fp, x2c);
                }
            }
            if (mode == 0) zout[row * DD + j] = 0.0f;
        }

        if (have_next) {
#pragma unroll
            for (int u = 0; u < 4; u++) hT[buf ^ 1][u][j * 4 + g] = pf[u];
        }
        __syncthreads();
        buf ^= 1;
    }
}

// ---------------------------------------------------------------------------
// edge kernel: 16 lanes per group, 2 consecutive edges per group per iter,
// edge indices software-pipelined; packed bf16x2 attention math.
// ---------------------------------------------------------------------------
struct EdgeVals {
    int sub, obj;
    float s, pd;
    float4 hx, y;
    float x2, y2, fac;
};

__device__ __forceinline__ void edge_load(
    const float* __restrict__ hidden, float4 wa, int l,
    int r_idx, int rel, int sub, int obj, EdgeVals& v)
{
    v.sub = sub; v.obj = obj;

    uint2 pb = __ldg((const uint2*)g_hs_projh  + sub   * 16 + l);
    uint2 rb = __ldg((const uint2*)g_rel_projh + rel   * 16 + l);
    uint2 qb = __ldg((const uint2*)g_qr_projh  + r_idx * 16 + l);

    // packed bf16x2: add 3 tables + relu, then unpack for f32 dot
    __nv_bfloat162 z2b; *(unsigned*)&z2b = 0u;
    __nv_bfloat162 t0 = __hmax2(__hadd2(__hadd2(*(__nv_bfloat162*)&pb.x,
                                                *(__nv_bfloat162*)&rb.x),
                                        *(__nv_bfloat162*)&qb.x), z2b);
    __nv_bfloat162 t1 = __hmax2(__hadd2(__hadd2(*(__nv_bfloat162*)&pb.y,
                                                *(__nv_bfloat162*)&rb.y),
                                        *(__nv_bfloat162*)&qb.y), z2b);
    unsigned u0 = *(unsigned*)&t0, u1 = *(unsigned*)&t1;
    float s = bflo(u0) * wa.x;
    s = fmaf(bfhi(u0), wa.y, s);
    s = fmaf(bflo(u1), wa.z, s);
    s = fmaf(bfhi(u1), wa.w, s);
    v.s = s;

    v.hx = __ldg((const float4*)hidden + sub * 16 + l);
    v.y  = __ldg((const float4*)g_hr_h + rel * 16 + l);
    float pd = v.hx.x * v.y.x;
    pd = fmaf(v.hx.y, v.y.y, pd);
    pd = fmaf(v.hx.z, v.y.z, pd);
    pd = fmaf(v.hx.w, v.y.w, pd);
    v.pd = pd;

    float2 scs = __ldg(&g_hs_sc[sub]);
    v.fac = scs.x; v.x2 = scs.y;
    v.y2  = __ldg(&g_hr_y2[rel]);
}

__device__ __forceinline__ void edge_finish(
    const EdgeVals& v, float* __restrict__ out, int l)
{
    float xy = v.fac * v.pd;
    float alpha = __fdividef(1.0f, 1.0f + __expf(-v.s));

    float A   = 1.0f + 2.0f * CC * xy + CC * v.y2;
    float B   = 1.0f - CC * v.x2;
    float den = fmaxf(1.0f + 2.0f * CC * xy + CC * CC * v.x2 * v.y2, 1e-15f);
    float inv = __fdividef(1.0f, den);
    float mm = fmaf(A * A, v.x2, fmaf(2.0f * A * B, xy, B * B * v.y2)) * inv * inv;
    mm = fmaxf(mm, 0.0f);
    float ps = 1.0f;
    if (mm > MN2) ps = MAXNORM * rsqrtf(mm);
    float z2 = CC * fminf(mm, MN2);
    float f  = artanh_ratio(z2);

    float sc = alpha * f * ps * inv;
    float sA = A * sc * v.fac;
    float sB = B * sc;

    float g0 = fmaf(sA, v.hx.x, sB * v.y.x);
    float g1 = fmaf(sA, v.hx.y, sB * v.y.y);
    float g2 = fmaf(sA, v.hx.z, sB * v.y.z);
    float g3 = fmaf(sA, v.hx.w, sB * v.y.w);

    float* dst = out + (long)v.obj * DD + l * 4;
    asm volatile("red.global.add.v4.f32 [%0], {%1,%2,%3,%4};"
                 :: "l"(dst), "f"(g0), "f"(g1), "f"(g2), "f"(g3) : "memory");
}

__global__ __launch_bounds__(256) void edge_kernel(
    const int* __restrict__ edges, const float* __restrict__ Wattn,
    const float* __restrict__ hidden, float* __restrict__ out, int n_edge)
{
    int l = threadIdx.x & 15;
    float4 wa = __ldg((const float4*)Wattn + l);
    int group  = (blockIdx.x * blockDim.x + threadIdx.x) >> 4;
    int stride = (gridDim.x * blockDim.x) >> 4;
    int npair  = (n_edge + 1) >> 1;

    int p = group;
    int2 c0a, c0b, c0c, c1a, c1b, c1c;
    if (p < npair) {
        const int2* e0 = (const int2*)edges + (long)(p * 2) * 3;
        c0a = __ldcs(e0); c0b = __ldcs(e0 + 1); c0c = __ldcs(e0 + 2);
        if (p * 2 + 1 < n_edge) {
            c1a = __ldcs(e0 + 3); c1b = __ldcs(e0 + 4); c1c = __ldcs(e0 + 5);
        } else { c1a = c0a; c1b = c0b; c1c = c0c; }
    }

    while (p < npair) {
        int2 i0a = c0a, i0b = c0b, i0c = c0c;
        int2 i1a = c1a, i1b = c1b, i1c = c1c;
        bool has1 = (p * 2 + 1) < n_edge;

        int pn = p + stride;
        if (pn < npair) {
            const int2* e0 = (const int2*)edges + (long)(pn * 2) * 3;
            c0a = __ldcs(e0); c0b = __ldcs(e0 + 1); c0c = __ldcs(e0 + 2);
            if (pn * 2 + 1 < n_edge) {
                c1a = __ldcs(e0 + 3); c1b = __ldcs(e0 + 4); c1c = __ldcs(e0 + 5);
            }
        }

        EdgeVals v0, v1;
        edge_load(hidden, wa, l, i0a.x, i0b.x, i0c.x, i0c.y, v0);
        if (has1) edge_load(hidden, wa, l, i1a.x, i1b.x, i1c.x, i1c.y, v1);
        else { v1.s = 0; v1.pd = 0; }

        float a = v0.s, b = v0.pd, c2 = v1.s, d = v1.pd;
#pragma unroll
        for (int o = 8; o; o >>= 1) {
            a  += __shfl_xor_sync(0xffffffffu, a,  o);
            b  += __shfl_xor_sync(0xffffffffu, b,  o);
            c2 += __shfl_xor_sync(0xffffffffu, c2, o);
            d  += __shfl_xor_sync(0xffffffffu, d,  o);
        }
        v0.s = a; v0.pd = b; v1.s = c2; v1.pd = d;

        edge_finish(v0, out, l);
        if (has1) edge_finish(v1, out, l);

        p = pn;
    }
}

// ---------------------------------------------------------------------------
// final: out[n] = logmap0(relu(expmap0(Wh @ agg[n])))  (in-place)
// Single fused reduction; double-buffered staging (1 barrier + 1 red-barrier).
// ---------------------------------------------------------------------------
__global__ __launch_bounds__(256) void final_kernel(
    const float* __restrict__ Wh, float* __restrict__ out, int n_node)
{
    __shared__ float Wst[DD][DD + 1];
    __shared__ __align__(16) float hT[2][4][DD * 4];
    __shared__ float red2[4][2][8];

    int t = threadIdx.x;
    for (int i = t; i < DD * DD; i += 256) Wst[i & 63][i >> 6] = Wh[i];

    int g = t >> 6, j = t & 63, half = (t >> 5) & 1;

    float pf[4];
    {
        int base = (blockIdx.x * TILES) * 16;
#pragma unroll
        for (int u = 0; u < 4; u++) {
            int row = base + g + 4 * u;
            pf[u] = (row < n_node) ? __ldg(&out[row * DD + j]) : 0.0f;
        }
    }

    int buf = 0;
    {
#pragma unroll
        for (int u = 0; u < 4; u++) hT[0][u][j * 4 + g] = pf[u];
        __syncthreads();
    }

    for (int tile = 0; tile < TILES; tile++) {
        int base = (blockIdx.x * TILES + tile) * 16;
        if (base >= n_node) break;

        int nbase = base + 16;
        bool have_next = (tile + 1 < TILES) && (nbase < n_node);
        if (have_next) {
#pragma unroll
            for (int u = 0; u < 4; u++) {
                int row = nbase + g + 4 * u;
                pf[u] = (row < n_node) ? __ldg(&out[row * DD + j]) : 0.0f;
            }
        }

        unsigned long long acc01 = 0ull, acc23 = 0ull;
#pragma unroll
        for (int k = 0; k < DD; k++) {
            float w = Wst[k][j];
            unsigned long long ww = pack2(w, w);
            ulonglong2 hh = *(const ulonglong2*)&hT[buf][g][k * 4];
            acc01 = fma2(ww, hh.x, acc01);
            acc23 = fma2(ww, hh.y, acc23);
        }
        float acc[4];
        unpack2(acc01, acc[0], acc[1]);
        unpack2(acc23, acc[2], acc[3]);

        // fused reduction: sum acc^2 and sum max(acc,0)^2 for 4 rows
        float sa[4], sp[4];
#pragma unroll
        for (int r = 0; r < 4; r++) {
            float ap = fmaxf(acc[r], 0.0f);
            sa[r] = acc[r] * acc[r];
            sp[r] = ap * ap;
        }
#pragma unroll
        for (int o = 16; o; o >>= 1) {
#pragma unroll
            for (int r = 0; r < 4; r++) {
                sa[r] += __shfl_xor_sync(0xffffffffu, sa[r], o);
                sp[r] += __shfl_xor_sync(0xffffffffu, sp[r], o);
            }
        }
        if ((t & 31) == 0) {
#pragma unroll
            for (int r = 0; r < 4; r++) {
                red2[g][half][r]     = sa[r];
                red2[g][half][4 + r] = sp[r];
            }
        }
        __syncthreads();

#pragma unroll
        for (int r = 0; r < 4; r++) {
            int row = base + g * 4 + r;
            if (row >= n_node) continue;
            float nv2 = red2[g][0][r]     + red2[g][1][r];
            float sp2 = red2[g][0][4 + r] + red2[g][1][4 + r];
            float z2  = CC * nv2;
            float fac = tanh_ratio(z2);
            float rn2 = fac * fac * nv2;
            float ps  = 1.0f;
            if (rn2 > MN2) ps = MAXNORM * rsqrtf(rn2);
            float fp  = fac * ps;
            float na2 = fp * fp * sp2;               // ||relu(expmap0)||^2
            float gg  = artanh_ratio(CC * na2);
            out[row * DD + j] = fp * fmaxf(acc[r], 0.0f) * gg;
        }

        if (have_next) {
#pragma unroll
            for (int u = 0; u < 4; u++) hT[buf ^ 1][u][j * 4 + g] = pf[u];
        }
        __syncthreads();
        buf ^= 1;
    }
}

// ---------------------------------------------------------------------------
extern "C" void kernel_launch(void* const* d_in, const int* in_sizes, int n_in,
                              void* d_out, int out_size)
{
    const float* hidden = (const float*)d_in[0];
    const int*   q_rel  = (const int*)  d_in[1];
    const int*   edges  = (const int*)  d_in[2];
    const float* rela   = (const float*)d_in[3];
    const float* Ws     = (const float*)d_in[4];
    const float* Wr     = (const float*)d_in[5];
    const float* Wqr    = (const float*)d_in[6];
    const float* Wqr_b  = (const float*)d_in[7];
    const float* Wattn  = (const float*)d_in[8];
    const float* Wh     = (const float*)d_in[9];
    float* out = (float*)d_out;

    int n_node  = in_sizes[0] / DD;
    int Bn      = in_sizes[1];
    int n_edge  = in_sizes[2] / 6;
    int n_vocab = in_sizes[3] / DD;

    int nb0 = (n_node  + 63) / 64;
    int nb1 = (n_vocab + 63) / 64;
    int nb2 = (Bn      + 63) / 64;

    prep_all<<<nb0 + nb1 + nb2, 256>>>(Ws, Wr, Wqr, hidden, rela, q_rel, Wqr_b,
                                       out, n_node, n_vocab, Bn, nb0, nb1);

    edge_kernel<<<2368, 256>>>(edges, Wattn, hidden, out, n_edge);

    final_kernel<<<(n_node + 63) / 64, 256>>>(Wh, out, n_node);
}